// round 9
// baseline (speedup 1.0000x reference)
#include <cuda_runtime.h>
#include <cuda_bf16.h>
#include <math.h>
#include <stdint.h>

#define T 2048
#define D 2048
#define NH 16
#define NKVH 4
#define HD 128
#define DH 1024
#define KVD 512
#define MEG (1024*1024)

__device__ float g_scratch[35 * MEG];

// ================= PTX helpers =================
__device__ __forceinline__ uint32_t smem_u32(const void* p) {
    uint32_t a;
    asm("{ .reg .u64 t; cvta.to.shared.u64 t, %1; cvt.u32.u64 %0, t; }" : "=r"(a) : "l"(p));
    return a;
}
#define CP16(s, g) asm volatile("cp.async.cg.shared.global [%0], [%1], 16;" \
    :: "r"(s), "l"(__cvta_generic_to_global(g)) : "memory")
#define CP_COMMIT() asm volatile("cp.async.commit_group;" ::: "memory")
#define CP_WAIT(n)  asm volatile("cp.async.wait_group %0;" :: "n"(n) : "memory")

__device__ __forceinline__ void ldsm_x4(uint32_t* r, uint32_t addr) {
    asm volatile("ldmatrix.sync.aligned.m8n8.x4.shared.b16 {%0,%1,%2,%3}, [%4];"
        : "=r"(r[0]), "=r"(r[1]), "=r"(r[2]), "=r"(r[3]) : "r"(addr));
}
__device__ __forceinline__ void ldsm_x4_t(uint32_t* r, uint32_t addr) {
    asm volatile("ldmatrix.sync.aligned.m8n8.x4.trans.shared.b16 {%0,%1,%2,%3}, [%4];"
        : "=r"(r[0]), "=r"(r[1]), "=r"(r[2]), "=r"(r[3]) : "r"(addr));
}
__device__ __forceinline__ void mma16816(float* d, const uint32_t* a, uint32_t b0, uint32_t b1) {
    asm volatile("mma.sync.aligned.m16n8k16.row.col.f32.bf16.bf16.f32 "
        "{%0,%1,%2,%3}, {%4,%5,%6,%7}, {%8,%9}, {%0,%1,%2,%3};"
        : "+f"(d[0]), "+f"(d[1]), "+f"(d[2]), "+f"(d[3])
        : "r"(a[0]), "r"(a[1]), "r"(a[2]), "r"(a[3]), "r"(b0), "r"(b1));
}
__device__ __forceinline__ float ex2(float x) {
    float y; asm("ex2.approx.ftz.f32 %0, %1;" : "=f"(y) : "f"(x)); return y;
}
__device__ __forceinline__ void hilo2(float a, float b, uint32_t& hi, uint32_t& lo) {
    __nv_bfloat162 h = __floats2bfloat162_rn(a, b);
    __nv_bfloat162 l = __floats2bfloat162_rn(a - __bfloat162float(h.x), b - __bfloat162float(h.y));
    hi = *(uint32_t*)&h; lo = *(uint32_t*)&l;
}

// ================= convert: fp32 -> bf16 hi/lo =================
__global__ void conv_a(const float* __restrict__ A, __nv_bfloat16* __restrict__ hi,
                       __nv_bfloat16* __restrict__ lo, int n4) {
    int i = blockIdx.x * blockDim.x + threadIdx.x;
    if (i >= n4) return;
    float4 a = ((const float4*)A)[i];
    __nv_bfloat162 h0 = __floats2bfloat162_rn(a.x, a.y);
    __nv_bfloat162 h1 = __floats2bfloat162_rn(a.z, a.w);
    __nv_bfloat162 l0 = __floats2bfloat162_rn(a.x - __bfloat162float(h0.x), a.y - __bfloat162float(h0.y));
    __nv_bfloat162 l1 = __floats2bfloat162_rn(a.z - __bfloat162float(h1.x), a.w - __bfloat162float(h1.y));
    ((__nv_bfloat162*)hi)[2 * i]     = h0;
    ((__nv_bfloat162*)hi)[2 * i + 1] = h1;
    ((__nv_bfloat162*)lo)[2 * i]     = l0;
    ((__nv_bfloat162*)lo)[2 * i + 1] = l1;
}

// ========== convert + transpose weights: W[K,N] -> Wt[N,K] bf16 hi/lo ==========
__global__ void conv_wt(const float* __restrict__ W, __nv_bfloat16* __restrict__ hi,
                        __nv_bfloat16* __restrict__ lo, int Kd, int Nd) {
    __shared__ float tile[32][33];
    int nb = blockIdx.x * 32, kb = blockIdx.y * 32;
    int tx = threadIdx.x & 31, ty0 = threadIdx.x >> 5;
    #pragma unroll
    for (int i = 0; i < 4; i++)
        tile[ty0 + 8 * i][tx] = W[(size_t)(kb + ty0 + 8 * i) * Nd + nb + tx];
    __syncthreads();
    #pragma unroll
    for (int i = 0; i < 4; i++) {
        int r = ty0 + 8 * i;
        float v = tile[tx][r];
        __nv_bfloat16 h = __float2bfloat16_rn(v);
        __nv_bfloat16 l = __float2bfloat16_rn(v - __bfloat162float(h));
        size_t o = (size_t)(nb + r) * Kd + kb + tx;
        hi[o] = h;
        lo[o] = l;
    }
}

// ================= bf16-split HMMA GEMM =================
#define SM_STRIDE 80
#define SM_SPLIT 10240
#define SM_BUF 40960
#define SMEMB 81920

template<int ACT>
__global__ __launch_bounds__(256, 1)
void gemm_mma(const __nv_bfloat16* __restrict__ Ahi, const __nv_bfloat16* __restrict__ Alo,
              const __nv_bfloat16* __restrict__ Bhi, const __nv_bfloat16* __restrict__ Blo,
              const float* __restrict__ bias, float* __restrict__ C,
              int M, int N, int K,
              const __nv_bfloat16* B2hi, const __nv_bfloat16* B2lo, float* C2) {
    extern __shared__ char smem[];
    if (blockIdx.z) { Bhi = B2hi; Blo = B2lo; C = C2; }
    const int tid = threadIdx.x, wid = tid >> 5, lane = tid & 31;
    const int m0 = blockIdx.y * 128, n0 = blockIdx.x * 128;
    const int wm = wid >> 2, wn = wid & 3;
    const uint32_t sb = smem_u32(smem);

    const int r0c = tid >> 2, c0c = (tid & 3);
    const int r1c = (tid + 256) >> 2, c1c = (tid & 3);

    auto fill = [&](int buf, int kc) {
        const int k0 = kc << 5;
        const uint32_t s0 = sb + buf * SM_BUF;
        uint32_t so0 = r0c * SM_STRIDE + c0c * 16;
        uint32_t so1 = r1c * SM_STRIDE + c1c * 16;
        const __nv_bfloat16* a0 = Ahi + (size_t)(m0 + r0c) * K + k0 + c0c * 8;
        const __nv_bfloat16* a1 = Ahi + (size_t)(m0 + r1c) * K + k0 + c1c * 8;
        const __nv_bfloat16* b0 = Bhi + (size_t)(n0 + r0c) * K + k0 + c0c * 8;
        const __nv_bfloat16* b1 = Bhi + (size_t)(n0 + r1c) * K + k0 + c1c * 8;
        size_t dAL = (size_t)(Alo - Ahi), dBL = (size_t)(Blo - Bhi);
        CP16(s0 + so0, a0); CP16(s0 + so1, a1);
        CP16(s0 + SM_SPLIT + so0, a0 + dAL); CP16(s0 + SM_SPLIT + so1, a1 + dAL);
        CP16(s0 + 2 * SM_SPLIT + so0, b0); CP16(s0 + 2 * SM_SPLIT + so1, b1);
        CP16(s0 + 3 * SM_SPLIT + so0, b0 + dBL); CP16(s0 + 3 * SM_SPLIT + so1, b1 + dBL);
        CP_COMMIT();
    };

    float acc[4][4][4] = {};
    const int KC = K >> 5;
    fill(0, 0);
    for (int kc = 0; kc < KC; kc++) {
        if (kc + 1 < KC) { fill((kc + 1) & 1, kc + 1); CP_WAIT(1); }
        else             { CP_WAIT(0); }
        __syncthreads();
        const uint32_t base = sb + (kc & 1) * SM_BUF;
        const uint32_t lrow = (lane & 15), lcol = (lane >> 4) * 16;
        #pragma unroll
        for (int kh = 0; kh < 2; kh++) {
            uint32_t ahi[4][4], alo[4][4], bhi[2][4], blo[2][4];
            #pragma unroll
            for (int mt = 0; mt < 4; mt++) {
                uint32_t ra = base + (wm * 64 + mt * 16 + lrow) * SM_STRIDE + kh * 32 + lcol;
                ldsm_x4(ahi[mt], ra);
                ldsm_x4(alo[mt], ra + SM_SPLIT);
            }
            #pragma unroll
            for (int nt = 0; nt < 2; nt++) {
                uint32_t rb = base + 2 * SM_SPLIT + (wn * 32 + nt * 16 + lrow) * SM_STRIDE + kh * 32 + lcol;
                ldsm_x4(bhi[nt], rb);
                ldsm_x4(blo[nt], rb + SM_SPLIT);
            }
            // 3 term-passes: 16 independent MMAs between any RAW reuse
            #pragma unroll
            for (int mt = 0; mt < 4; mt++)
                #pragma unroll
                for (int j = 0; j < 4; j++)
                    mma16816(acc[mt][j], ahi[mt], bhi[j >> 1][j & 1], bhi[j >> 1][2 + (j & 1)]);
            #pragma unroll
            for (int mt = 0; mt < 4; mt++)
                #pragma unroll
                for (int j = 0; j < 4; j++)
                    mma16816(acc[mt][j], ahi[mt], blo[j >> 1][j & 1], blo[j >> 1][2 + (j & 1)]);
            #pragma unroll
            for (int mt = 0; mt < 4; mt++)
                #pragma unroll
                for (int j = 0; j < 4; j++)
                    mma16816(acc[mt][j], alo[mt], bhi[j >> 1][j & 1], bhi[j >> 1][2 + (j & 1)]);
        }
        __syncthreads();
    }

    const int erow = m0 + wm * 64 + (lane >> 2);
    const int ecol = n0 + wn * 32 + (lane & 3) * 2;
    #pragma unroll
    for (int mt = 0; mt < 4; mt++)
        #pragma unroll
        for (int j = 0; j < 4; j++) {
            int r = erow + mt * 16, c = ecol + j * 8;
            float v0 = acc[mt][j][0], v1 = acc[mt][j][1];
            float v2 = acc[mt][j][2], v3 = acc[mt][j][3];
            if (ACT) {
                float b0 = bias[c], b1 = bias[c + 1];
                v0 += b0; v1 += b1; v2 += b0; v3 += b1;
                v0 = v0 / (1.f + expf(-v0)); v1 = v1 / (1.f + expf(-v1));
                v2 = v2 / (1.f + expf(-v2)); v3 = v3 / (1.f + expf(-v3));
            }
            *(float2*)(C + (size_t)r * N + c)       = make_float2(v0, v1);
            *(float2*)(C + (size_t)(r + 8) * N + c) = make_float2(v2, v3);
        }
}

// ================= chunked causal EMA =================
__global__ void ema1_kernel(const float* __restrict__ x, float* __restrict__ l2,
                            float* __restrict__ carry) {
    int c = blockIdx.x;
    int d = blockIdx.y * 256 + threadIdx.x;
    const float beta = 0.9f, om = 0.1f;
    float m = 0.f;
    int t0 = c * 128;
    for (int t = t0; t < t0 + 128; t++) {
        m = beta * m + om * x[(size_t)t * D + d];
        l2[(size_t)t * D + d] = m;
    }
    carry[c * D + d] = m;
}
__global__ void ema2_kernel(const float* __restrict__ carry, float* __restrict__ cpref) {
    int d = blockIdx.x * 256 + threadIdx.x;
    const float b128 = 1.3900845e-06f;  // 0.9^128
    float p = 0.f;
    #pragma unroll
    for (int c = 0; c < 16; c++) {
        cpref[c * D + d] = p;
        p = carry[c * D + d] + b128 * p;
    }
}

// ================= router =================
__global__ void router_kernel(const float* __restrict__ h, const float* __restrict__ Wr2,
                              const float* __restrict__ br2, float* __restrict__ lam) {
    int t = blockIdx.x * (blockDim.x >> 5) + (threadIdx.x >> 5);
    int lane = threadIdx.x & 31;
    if (t >= T) return;
    const float* hp = h + (size_t)t * DH;
    float z0 = 0.f, z1 = 0.f;
    for (int i = lane; i < DH; i += 32) {
        float hv = hp[i];
        z0 += hv * Wr2[i * 2 + 0];
        z1 += hv * Wr2[i * 2 + 1];
    }
    #pragma unroll
    for (int off = 16; off; off >>= 1) {
        z0 += __shfl_xor_sync(0xffffffffu, z0, off);
        z1 += __shfl_xor_sync(0xffffffffu, z1, off);
    }
    if (lane == 0) {
        z0 += br2[0]; z1 += br2[1];
        float mx = fmaxf(z0, z1);
        float e0 = expf(z0 - mx), e1 = expf(z1 - mx);
        float inv = 1.f / (e0 + e1);
        lam[t * 2 + 0] = e0 * inv;
        lam[t * 2 + 1] = e1 * inv;
    }
}

// ====== fuse (with EMA carry fixup) ======
__global__ void fuse_kernel(const float* __restrict__ x, const float* __restrict__ l2,
                            const float* __restrict__ cpref, const float* __restrict__ lam,
                            float* __restrict__ fused) {
    int idx = blockIdx.x * blockDim.x + threadIdx.x;
    if (idx >= T * D) return;
    int t = idx >> 11, d = idx & 2047;
    int c = t >> 7, tl = t & 127;
    const float LOGB = -0.10536051565f;  // ln(0.9)
    float l2v = l2[idx] + __expf((float)(tl + 1) * LOGB) * cpref[c * D + d];
    fused[idx] = lam[t * 2] * x[idx] + lam[t * 2 + 1] * l2v;
}

// ================= RoPE in place =================
__global__ void rope_kernel(float* __restrict__ x, int heads) {
    int idx = blockIdx.x * blockDim.x + threadIdx.x;
    int total = T * heads * 64;
    if (idx >= total) return;
    int j = idx & 63;
    int hh = (idx >> 6) % heads;
    int t = idx / (heads * 64);
    float* p = x + (size_t)t * heads * HD + hh * HD;
    float inv = expf(-9.210340371976184f * (2.f * j / 128.f));
    float ang = (float)t * inv;
    float cs = cosf(ang), sn = sinf(ang);
    float a = p[j], b = p[j + 64];
    p[j]      = a * cs - b * sn;
    p[j + 64] = b * cs + a * sn;
}

// ================= tensor-core flash attention =================
#define FA_STR 272
#define FA_QSZ 17408
#define FA_KVB 69632
#define FA_SMEM 174080

__global__ __launch_bounds__(128, 1)
void fattn_kernel(const __nv_bfloat16* __restrict__ Qhi, const __nv_bfloat16* __restrict__ Qlo,
                  const __nv_bfloat16* __restrict__ Khi, const __nv_bfloat16* __restrict__ Klo,
                  const __nv_bfloat16* __restrict__ Vhi, const __nv_bfloat16* __restrict__ Vlo,
                  float* __restrict__ o) {
    extern __shared__ char smem[];
    const int tid = threadIdx.x, wid = tid >> 5, lane = tid & 31;
    const int qt = (int)(gridDim.x - 1 - blockIdx.x);
    const int head = blockIdx.y;
    const int kvh = head >> 2;
    const uint32_t sb = smem_u32(smem);
    const int g = lane >> 2, tq = lane & 3;
    const uint32_t lrow = lane & 15, lcol = (lane >> 4) * 16;

    {
        const size_t qoff = (size_t)(qt * 64) * D + head * HD;
        const size_t dQ = (size_t)(Qlo - Qhi);
        #pragma unroll
        for (int i = 0; i < 8; i++) {
            int idx = tid + i * 128;
            int r = idx >> 4, c = idx & 15;
            const __nv_bfloat16* src = Qhi + qoff + (size_t)r * D + c * 8;
            uint32_t dst = sb + r * FA_STR + c * 16;
            CP16(dst, src);
            CP16(dst + FA_QSZ, src + dQ);
        }
        CP_COMMIT();
    }

    const int kts = qt + 1;
    const size_t dK = (size_t)(Klo - Khi), dV = (size_t)(Vlo - Vhi);
    auto loadKV = [&](int kt) {
        const size_t koff = (size_t)(kt * 64) * KVD + kvh * HD;
        const uint32_t kb = sb + 2 * FA_QSZ + (kt & 1) * FA_KVB;
        #pragma unroll
        for (int i = 0; i < 8; i++) {
            int idx = tid + i * 128;
            int r = idx >> 4, c = idx & 15;
            size_t so = koff + (size_t)r * KVD + c * 8;
            uint32_t dst = kb + r * FA_STR + c * 16;
            CP16(dst,                 Khi + so);
            CP16(dst + FA_QSZ,        Khi + so + dK);
            CP16(dst + 2 * FA_QSZ,    Vhi + so);
            CP16(dst + 3 * FA_QSZ,    Vhi + so + dV);
        }
        CP_COMMIT();
    };
    loadKV(0);

    float m0 = -1e30f, m1 = -1e30f, l0 = 0.f, l1 = 0.f;
    float oa[16][4] = {};
    const float SC2 = 0.08838834764831845f * 1.4426950408889634f;

    for (int kt = 0; kt < kts; kt++) {
        if (kt + 1 < kts) { loadKV(kt + 1); CP_WAIT(1); }
        else              { CP_WAIT(0); }
        __syncthreads();
        const uint32_t kb = sb + 2 * FA_QSZ + (kt & 1) * FA_KVB;

        // ---- S = Q @ K^T (3 term-passes, 8 independent accs each) ----
        float s[8][4];
        #pragma unroll
        for (int nf = 0; nf < 8; nf++)
            s[nf][0] = s[nf][1] = s[nf][2] = s[nf][3] = 0.f;
        #pragma unroll
        for (int ks = 0; ks < 8; ks++) {
            uint32_t ahi[4], alo[4], bhi[4][4], blo[4][4];
            uint32_t ra = sb + (wid * 16 + lrow) * FA_STR + lcol + ks * 32;
            ldsm_x4(ahi, ra);
            ldsm_x4(alo, ra + FA_QSZ);
            #pragma unroll
            for (int bt = 0; bt < 4; bt++) {
                uint32_t rb = kb + (bt * 16 + lrow) * FA_STR + lcol + ks * 32;
                ldsm_x4(bhi[bt], rb);
                ldsm_x4(blo[bt], rb + FA_QSZ);
            }
            #pragma unroll
            for (int nf = 0; nf < 8; nf++)
                mma16816(s[nf], ahi, bhi[nf >> 1][nf & 1], bhi[nf >> 1][2 + (nf & 1)]);
            #pragma unroll
            for (int nf = 0; nf < 8; nf++)
                mma16816(s[nf], ahi, blo[nf >> 1][nf & 1], blo[nf >> 1][2 + (nf & 1)]);
            #pragma unroll
            for (int nf = 0; nf < 8; nf++)
                mma16816(s[nf], alo, bhi[nf >> 1][nf & 1], bhi[nf >> 1][2 + (nf & 1)]);
        }

        if (kt == qt) {
            int r0 = wid * 16 + g;
            #pragma unroll
            for (int nf = 0; nf < 8; nf++) {
                int c0 = nf * 8 + tq * 2;
                if (c0 > r0)         s[nf][0] = -1e30f;
                if (c0 + 1 > r0)     s[nf][1] = -1e30f;
                if (c0 > r0 + 8)     s[nf][2] = -1e30f;
                if (c0 + 1 > r0 + 8) s[nf][3] = -1e30f;
            }
        }

        float mx0 = -1e30f, mx1 = -1e30f;
        #pragma unroll
        for (int nf = 0; nf < 8; nf++) {
            mx0 = fmaxf(mx0, fmaxf(s[nf][0], s[nf][1]));
            mx1 = fmaxf(mx1, fmaxf(s[nf][2], s[nf][3]));
        }
        mx0 = fmaxf(mx0, __shfl_xor_sync(0xffffffffu, mx0, 1));
        mx0 = fmaxf(mx0, __shfl_xor_sync(0xffffffffu, mx0, 2));
        mx1 = fmaxf(mx1, __shfl_xor_sync(0xffffffffu, mx1, 1));
        mx1 = fmaxf(mx1, __shfl_xor_sync(0xffffffffu, mx1, 2));
        float mn0 = fmaxf(m0, mx0), mn1 = fmaxf(m1, mx1);
        float corr0 = ex2((m0 - mn0) * SC2);
        float corr1 = ex2((m1 - mn1) * SC2);
        m0 = mn0; m1 = mn1;
        l0 *= corr0; l1 *= corr1;
        #pragma unroll
        for (int nf = 0; nf < 8; nf++) {
            s[nf][0] = ex2((s[nf][0] - m0) * SC2);
            s[nf][1] = ex2((s[nf][1] - m0) * SC2);
            s[nf][2] = ex2((s[nf][2] - m1) * SC2);
            s[nf][3] = ex2((s[nf][3] - m1) * SC2);
            l0 += s[nf][0] + s[nf][1];
            l1 += s[nf][2] + s[nf][3];
        }
        #pragma unroll
        for (int nf = 0; nf < 16; nf++) {
            oa[nf][0] *= corr0; oa[nf][1] *= corr0;
            oa[nf][2] *= corr1; oa[nf][3] *= corr1;
        }

        // ---- O += P @ V (nb pairs: 4 independent accs per term-pass) ----
        #pragma unroll
        for (int pk = 0; pk < 4; pk++) {
            uint32_t pahi[4], palo[4];
            hilo2(s[2 * pk][0],     s[2 * pk][1],     pahi[0], palo[0]);
            hilo2(s[2 * pk][2],     s[2 * pk][3],     pahi[1], palo[1]);
            hilo2(s[2 * pk + 1][0], s[2 * pk + 1][1], pahi[2], palo[2]);
            hilo2(s[2 * pk + 1][2], s[2 * pk + 1][3], pahi[3], palo[3]);
            #pragma unroll
            for (int nbp = 0; nbp < 4; nbp++) {
                int nb0 = 2 * nbp, nb1 = 2 * nbp + 1;
                uint32_t vh0[4], vl0[4], vh1[4], vl1[4];
                uint32_t va0 = kb + 2 * FA_QSZ + (pk * 16 + lrow) * FA_STR + nb0 * 32 + lcol;
                uint32_t va1 = kb + 2 * FA_QSZ + (pk * 16 + lrow) * FA_STR + nb1 * 32 + lcol;
                ldsm_x4_t(vh0, va0);
                ldsm_x4_t(vh1, va1);
                ldsm_x4_t(vl0, va0 + FA_QSZ);
                ldsm_x4_t(vl1, va1 + FA_QSZ);
                mma16816(oa[2 * nb0],     pahi, vh0[0], vh0[1]);
                mma16816(oa[2 * nb0 + 1], pahi, vh0[2], vh0[3]);
                mma16816(oa[2 * nb1],     pahi, vh1[0], vh1[1]);
                mma16816(oa[2 * nb1 + 1], pahi, vh1[2], vh1[3]);
                mma16816(oa[2 * nb0],     pahi, vl0[0], vl0[1]);
                mma16816(oa[2 * nb0 + 1], pahi, vl0[2], vl0[3]);
                mma16816(oa[2 * nb1],     pahi, vl1[0], vl1[1]);
                mma16816(oa[2 * nb1 + 1], pahi, vl1[2], vl1[3]);
                mma16816(oa[2 * nb0],     palo, vh0[0], vh0[1]);
                mma16816(oa[2 * nb0 + 1], palo, vh0[2], vh0[3]);
                mma16816(oa[2 * nb1],     palo, vh1[0], vh1[1]);
                mma16816(oa[2 * nb1 + 1], palo, vh1[2], vh1[3]);
            }
        }
        __syncthreads();
    }

    l0 += __shfl_xor_sync(0xffffffffu, l0, 1);
    l0 += __shfl_xor_sync(0xffffffffu, l0, 2);
    l1 += __shfl_xor_sync(0xffffffffu, l1, 1);
    l1 += __shfl_xor_sync(0xffffffffu, l1, 2);
    float inv0 = 1.f / l0, inv1 = 1.f / l1;
    int row0 = qt * 64 + wid * 16 + g;
    float* b0 = o + (size_t)row0 * D + head * HD + tq * 2;
    float* b1 = b0 + 8 * D;
    #pragma unroll
    for (int nf = 0; nf < 16; nf++) {
        *(float2*)(b0 + nf * 8) = make_float2(oa[nf][0] * inv0, oa[nf][1] * inv0);
        *(float2*)(b1 + nf * 8) = make_float2(oa[nf][2] * inv1, oa[nf][3] * inv1);
    }
}

// ================= launcher =================
extern "C" void kernel_launch(void* const* d_in, const int* in_sizes, int n_in,
                              void* d_out, int out_size) {
    const float* hs  = (const float*)d_in[0];
    const float* Wq  = (const float*)d_in[1];
    const float* Wk  = (const float*)d_in[2];
    const float* Wv  = (const float*)d_in[3];
    const float* Wo  = (const float*)d_in[4];
    const float* Wr1 = (const float*)d_in[5];
    const float* br1 = (const float*)d_in[6];
    const float* Wr2 = (const float*)d_in[7];
    const float* br2 = (const float*)d_in[8];
    float* out = (float*)d_out;

    float* S;
    cudaGetSymbolAddress((void**)&S, g_scratch);
    float* q     = S;
    float* l2    = S + 4 * MEG;
    float* h     = S + 8 * MEG;
    float* fused = S + 10 * MEG;
    float* kbuf  = S + 14 * MEG;
    float* vbuf  = S + 15 * MEG;
    float* ao    = S + 16 * MEG;
    float* lam   = S + 20 * MEG;
    float* carry = lam + 4096;
    float* cpref = carry + 32768;
    __nv_bfloat16* Ahi = (__nv_bfloat16*)(S + 20 * MEG + 131072);
    __nv_bfloat16* Alo = (__nv_bfloat16*)(S + 22 * MEG + 131072);
    __nv_bfloat16* Whi = (__nv_bfloat16*)(S + 24 * MEG + 131072);
    __nv_bfloat16* Wlo = (__nv_bfloat16*)(S + 26 * MEG + 131072);
    __nv_bfloat16* QhiB = (__nv_bfloat16*)(S + 29 * MEG);
    __nv_bfloat16* QloB = (__nv_bfloat16*)(S + 31 * MEG);
    __nv_bfloat16* KhiB = (__nv_bfloat16*)(S + 33 * MEG);
    __nv_bfloat16* KloB = (__nv_bfloat16*)(S + 33 * MEG + 512 * 1024);
    __nv_bfloat16* VhiB = (__nv_bfloat16*)(S + 34 * MEG);
    __nv_bfloat16* VloB = (__nv_bfloat16*)(S + 34 * MEG + 512 * 1024);

    cudaFuncSetAttribute(gemm_mma<0>, cudaFuncAttributeMaxDynamicSharedMemorySize, SMEMB);
    cudaFuncSetAttribute(gemm_mma<1>, cudaFuncAttributeMaxDynamicSharedMemorySize, SMEMB);
    cudaFuncSetAttribute(fattn_kernel, cudaFuncAttributeMaxDynamicSharedMemorySize, FA_SMEM);

    // ---- q = hs @ Wq ----
    conv_a<<<(T * D / 4 + 255) / 256, 256>>>(hs, Ahi, Alo, T * D / 4);
    conv_wt<<<dim3(D / 32, D / 32), 256>>>(Wq, Whi, Wlo, D, D);
    gemm_mma<0><<<dim3(D / 128, T / 128, 1), 256, SMEMB>>>(
        Ahi, Alo, Whi, Wlo, nullptr, q, T, D, D, nullptr, nullptr, nullptr);

    // ---- EMA ----
    ema1_kernel<<<dim3(16, 8), 256>>>(hs, l2, carry);
    ema2_kernel<<<8, 256>>>(carry, cpref);

    // ---- h = silu(q @ Wr1 + br1) ----
    conv_a<<<(T * D / 4 + 255) / 256, 256>>>(q, Ahi, Alo, T * D / 4);
    conv_wt<<<dim3(DH / 32, D / 32), 256>>>(Wr1, Whi, Wlo, D, DH);
    gemm_mma<1><<<dim3(DH / 128, T / 128, 1), 256, SMEMB>>>(
        Ahi, Alo, Whi, Wlo, br1, h, T, DH, D, nullptr, nullptr, nullptr);

    // ---- lam, fused ----
    router_kernel<<<T / 8, 256>>>(h, Wr2, br2, lam);
    fuse_kernel<<<(T * D + 255) / 256, 256>>>(hs, l2, cpref, lam, fused);

    // ---- k = fused @ Wk, v = fused @ Wv ----
    conv_a<<<(T * D / 4 + 255) / 256, 256>>>(fused, Ahi, Alo, T * D / 4);
    __nv_bfloat16* WkHi = Whi;
    __nv_bfloat16* WkLo = Whi + KVD * D;
    __nv_bfloat16* WvHi = Wlo;
    __nv_bfloat16* WvLo = Wlo + KVD * D;
    conv_wt<<<dim3(KVD / 32, D / 32), 256>>>(Wk, WkHi, WkLo, D, KVD);
    conv_wt<<<dim3(KVD / 32, D / 32), 256>>>(Wv, WvHi, WvLo, D, KVD);
    gemm_mma<0><<<dim3(KVD / 128, T / 128, 2), 256, SMEMB>>>(
        Ahi, Alo, WkHi, WkLo, nullptr, kbuf, T, KVD, D, WvHi, WvLo, vbuf);

    // ---- RoPE ----
    rope_kernel<<<(T * NH * 64 + 255) / 256, 256>>>(q, NH);
    rope_kernel<<<(T * NKVH * 64 + 255) / 256, 256>>>(kbuf, NKVH);

    // ---- convert q/k/v to bf16 hi/lo for flash attention ----
    conv_a<<<(T * D / 4 + 255) / 256, 256>>>(q, QhiB, QloB, T * D / 4);
    conv_a<<<(T * KVD / 4 + 255) / 256, 256>>>(kbuf, KhiB, KloB, T * KVD / 4);
    conv_a<<<(T * KVD / 4 + 255) / 256, 256>>>(vbuf, VhiB, VloB, T * KVD / 4);

    // ---- flash attention ----
    fattn_kernel<<<dim3(T / 64, NH), 128, FA_SMEM>>>(QhiB, QloB, KhiB, KloB, VhiB, VloB, ao);

    // ---- out = ao @ Wo ----
    conv_a<<<(T * D / 4 + 255) / 256, 256>>>(ao, Ahi, Alo, T * D / 4);
    conv_wt<<<dim3(D / 32, D / 32), 256>>>(Wo, Whi, Wlo, D, D);
    gemm_mma<0><<<dim3(D / 128, T / 128, 1), 256, SMEMB>>>(
        Ahi, Alo, Whi, Wlo, nullptr, out, T, D, D, nullptr, nullptr, nullptr);
}

// round 10
// speedup vs baseline: 1.0014x; 1.0014x over previous
#include <cuda_runtime.h>
#include <cuda_bf16.h>
#include <math.h>
#include <stdint.h>

#define T 2048
#define D 2048
#define NH 16
#define NKVH 4
#define HD 128
#define DH 1024
#define KVD 512
#define MEG (1024*1024)

__device__ float g_scratch[35 * MEG];

// ================= PTX helpers =================
__device__ __forceinline__ uint32_t smem_u32(const void* p) {
    uint32_t a;
    asm("{ .reg .u64 t; cvta.to.shared.u64 t, %1; cvt.u32.u64 %0, t; }" : "=r"(a) : "l"(p));
    return a;
}
#define CP16(s, g) asm volatile("cp.async.cg.shared.global [%0], [%1], 16;" \
    :: "r"(s), "l"(__cvta_generic_to_global(g)) : "memory")
#define CP_COMMIT() asm volatile("cp.async.commit_group;" ::: "memory")
#define CP_WAIT(n)  asm volatile("cp.async.wait_group %0;" :: "n"(n) : "memory")

__device__ __forceinline__ void ldsm_x4(uint32_t* r, uint32_t addr) {
    asm volatile("ldmatrix.sync.aligned.m8n8.x4.shared.b16 {%0,%1,%2,%3}, [%4];"
        : "=r"(r[0]), "=r"(r[1]), "=r"(r[2]), "=r"(r[3]) : "r"(addr));
}
__device__ __forceinline__ void ldsm_x4_t(uint32_t* r, uint32_t addr) {
    asm volatile("ldmatrix.sync.aligned.m8n8.x4.trans.shared.b16 {%0,%1,%2,%3}, [%4];"
        : "=r"(r[0]), "=r"(r[1]), "=r"(r[2]), "=r"(r[3]) : "r"(addr));
}
__device__ __forceinline__ void mma16816(float* d, const uint32_t* a, uint32_t b0, uint32_t b1) {
    asm volatile("mma.sync.aligned.m16n8k16.row.col.f32.bf16.bf16.f32 "
        "{%0,%1,%2,%3}, {%4,%5,%6,%7}, {%8,%9}, {%0,%1,%2,%3};"
        : "+f"(d[0]), "+f"(d[1]), "+f"(d[2]), "+f"(d[3])
        : "r"(a[0]), "r"(a[1]), "r"(a[2]), "r"(a[3]), "r"(b0), "r"(b1));
}
__device__ __forceinline__ float ex2(float x) {
    float y; asm("ex2.approx.ftz.f32 %0, %1;" : "=f"(y) : "f"(x)); return y;
}
__device__ __forceinline__ void hilo2(float a, float b, uint32_t& hi, uint32_t& lo) {
    __nv_bfloat162 h = __floats2bfloat162_rn(a, b);
    __nv_bfloat162 l = __floats2bfloat162_rn(a - __bfloat162float(h.x), b - __bfloat162float(h.y));
    hi = *(uint32_t*)&h; lo = *(uint32_t*)&l;
}

// ================= convert: fp32 -> bf16 hi/lo =================
__global__ void conv_a(const float* __restrict__ A, __nv_bfloat16* __restrict__ hi,
                       __nv_bfloat16* __restrict__ lo, int n4) {
    int i = blockIdx.x * blockDim.x + threadIdx.x;
    if (i >= n4) return;
    float4 a = ((const float4*)A)[i];
    uint32_t h0, l0, h1, l1;
    hilo2(a.x, a.y, h0, l0);
    hilo2(a.z, a.w, h1, l1);
    ((uint32_t*)hi)[2 * i] = h0;  ((uint32_t*)hi)[2 * i + 1] = h1;
    ((uint32_t*)lo)[2 * i] = l0;  ((uint32_t*)lo)[2 * i + 1] = l1;
}

// ========== convert + transpose weights: W[K,N] -> Wt[N,K] bf16 hi/lo ==========
__global__ void conv_wt(const float* __restrict__ W, __nv_bfloat16* __restrict__ hi,
                        __nv_bfloat16* __restrict__ lo, int Kd, int Nd) {
    __shared__ float tile[32][33];
    int nb = blockIdx.x * 32, kb = blockIdx.y * 32;
    int tx = threadIdx.x & 31, ty0 = threadIdx.x >> 5;
    #pragma unroll
    for (int i = 0; i < 4; i++)
        tile[ty0 + 8 * i][tx] = W[(size_t)(kb + ty0 + 8 * i) * Nd + nb + tx];
    __syncthreads();
    #pragma unroll
    for (int i = 0; i < 4; i++) {
        int r = ty0 + 8 * i;
        float v = tile[tx][r];
        __nv_bfloat16 h = __float2bfloat16_rn(v);
        __nv_bfloat16 l = __float2bfloat16_rn(v - __bfloat162float(h));
        size_t o = (size_t)(nb + r) * Kd + kb + tx;
        hi[o] = h;
        lo[o] = l;
    }
}

// ================= bf16-split HMMA GEMM (+ optional hi/lo output) =================
#define SM_STRIDE 80
#define SM_SPLIT 10240
#define SM_BUF 40960
#define SMEMB 81920

template<int ACT>
__global__ __launch_bounds__(256, 1)
void gemm_mma(const __nv_bfloat16* __restrict__ Ahi, const __nv_bfloat16* __restrict__ Alo,
              const __nv_bfloat16* __restrict__ Bhi, const __nv_bfloat16* __restrict__ Blo,
              const float* __restrict__ bias, float* __restrict__ C,
              __nv_bfloat16* __restrict__ Chi, __nv_bfloat16* __restrict__ Clo,
              int M, int N, int K,
              const __nv_bfloat16* B2hi, const __nv_bfloat16* B2lo, float* C2,
              __nv_bfloat16* C2hi, __nv_bfloat16* C2lo) {
    extern __shared__ char smem[];
    if (blockIdx.z) { Bhi = B2hi; Blo = B2lo; C = C2; Chi = C2hi; Clo = C2lo; }
    const int tid = threadIdx.x, wid = tid >> 5, lane = tid & 31;
    const int m0 = blockIdx.y * 128, n0 = blockIdx.x * 128;
    const int wm = wid >> 2, wn = wid & 3;
    const uint32_t sb = smem_u32(smem);

    const int r0c = tid >> 2, c0c = (tid & 3);
    const int r1c = (tid + 256) >> 2, c1c = (tid & 3);

    auto fill = [&](int buf, int kc) {
        const int k0 = kc << 5;
        const uint32_t s0 = sb + buf * SM_BUF;
        uint32_t so0 = r0c * SM_STRIDE + c0c * 16;
        uint32_t so1 = r1c * SM_STRIDE + c1c * 16;
        const __nv_bfloat16* a0 = Ahi + (size_t)(m0 + r0c) * K + k0 + c0c * 8;
        const __nv_bfloat16* a1 = Ahi + (size_t)(m0 + r1c) * K + k0 + c1c * 8;
        const __nv_bfloat16* b0 = Bhi + (size_t)(n0 + r0c) * K + k0 + c0c * 8;
        const __nv_bfloat16* b1 = Bhi + (size_t)(n0 + r1c) * K + k0 + c1c * 8;
        size_t dAL = (size_t)(Alo - Ahi), dBL = (size_t)(Blo - Bhi);
        CP16(s0 + so0, a0); CP16(s0 + so1, a1);
        CP16(s0 + SM_SPLIT + so0, a0 + dAL); CP16(s0 + SM_SPLIT + so1, a1 + dAL);
        CP16(s0 + 2 * SM_SPLIT + so0, b0); CP16(s0 + 2 * SM_SPLIT + so1, b1);
        CP16(s0 + 3 * SM_SPLIT + so0, b0 + dBL); CP16(s0 + 3 * SM_SPLIT + so1, b1 + dBL);
        CP_COMMIT();
    };

    float acc[4][4][4] = {};
    const int KC = K >> 5;
    fill(0, 0);
    for (int kc = 0; kc < KC; kc++) {
        if (kc + 1 < KC) { fill((kc + 1) & 1, kc + 1); CP_WAIT(1); }
        else             { CP_WAIT(0); }
        __syncthreads();
        const uint32_t base = sb + (kc & 1) * SM_BUF;
        const uint32_t lrow = (lane & 15), lcol = (lane >> 4) * 16;
        #pragma unroll
        for (int kh = 0; kh < 2; kh++) {
            uint32_t ahi[4][4], alo[4][4], bhi[2][4], blo[2][4];
            #pragma unroll
            for (int mt = 0; mt < 4; mt++) {
                uint32_t ra = base + (wm * 64 + mt * 16 + lrow) * SM_STRIDE + kh * 32 + lcol;
                ldsm_x4(ahi[mt], ra);
                ldsm_x4(alo[mt], ra + SM_SPLIT);
            }
            #pragma unroll
            for (int nt = 0; nt < 2; nt++) {
                uint32_t rb = base + 2 * SM_SPLIT + (wn * 32 + nt * 16 + lrow) * SM_STRIDE + kh * 32 + lcol;
                ldsm_x4(bhi[nt], rb);
                ldsm_x4(blo[nt], rb + SM_SPLIT);
            }
            #pragma unroll
            for (int mt = 0; mt < 4; mt++)
                #pragma unroll
                for (int j = 0; j < 4; j++)
                    mma16816(acc[mt][j], ahi[mt], bhi[j >> 1][j & 1], bhi[j >> 1][2 + (j & 1)]);
            #pragma unroll
            for (int mt = 0; mt < 4; mt++)
                #pragma unroll
                for (int j = 0; j < 4; j++)
                    mma16816(acc[mt][j], ahi[mt], blo[j >> 1][j & 1], blo[j >> 1][2 + (j & 1)]);
            #pragma unroll
            for (int mt = 0; mt < 4; mt++)
                #pragma unroll
                for (int j = 0; j < 4; j++)
                    mma16816(acc[mt][j], alo[mt], bhi[j >> 1][j & 1], bhi[j >> 1][2 + (j & 1)]);
        }
        __syncthreads();
    }

    const int erow = m0 + wm * 64 + (lane >> 2);
    const int ecol = n0 + wn * 32 + (lane & 3) * 2;
    #pragma unroll
    for (int mt = 0; mt < 4; mt++)
        #pragma unroll
        for (int j = 0; j < 4; j++) {
            int r = erow + mt * 16, c = ecol + j * 8;
            float v0 = acc[mt][j][0], v1 = acc[mt][j][1];
            float v2 = acc[mt][j][2], v3 = acc[mt][j][3];
            if (ACT) {
                float b0 = bias[c], b1 = bias[c + 1];
                v0 += b0; v1 += b1; v2 += b0; v3 += b1;
                v0 = v0 / (1.f + expf(-v0)); v1 = v1 / (1.f + expf(-v1));
                v2 = v2 / (1.f + expf(-v2)); v3 = v3 / (1.f + expf(-v3));
            }
            *(float2*)(C + (size_t)r * N + c)       = make_float2(v0, v1);
            *(float2*)(C + (size_t)(r + 8) * N + c) = make_float2(v2, v3);
            if (Chi) {
                uint32_t hw, lw;
                hilo2(v0, v1, hw, lw);
                *(uint32_t*)(Chi + (size_t)r * N + c) = hw;
                *(uint32_t*)(Clo + (size_t)r * N + c) = lw;
                hilo2(v2, v3, hw, lw);
                *(uint32_t*)(Chi + (size_t)(r + 8) * N + c) = hw;
                *(uint32_t*)(Clo + (size_t)(r + 8) * N + c) = lw;
            }
        }
}

// ================= chunked causal EMA =================
__global__ void ema1_kernel(const float* __restrict__ x, float* __restrict__ l2,
                            float* __restrict__ carry) {
    int c = blockIdx.x;
    int d = blockIdx.y * 256 + threadIdx.x;
    const float beta = 0.9f, om = 0.1f;
    float m = 0.f;
    int t0 = c * 128;
    for (int t = t0; t < t0 + 128; t++) {
        m = beta * m + om * x[(size_t)t * D + d];
        l2[(size_t)t * D + d] = m;
    }
    carry[c * D + d] = m;
}
__global__ void ema2_kernel(const float* __restrict__ carry, float* __restrict__ cpref) {
    int d = blockIdx.x * 256 + threadIdx.x;
    const float b128 = 1.3900845e-06f;  // 0.9^128
    float p = 0.f;
    #pragma unroll
    for (int c = 0; c < 16; c++) {
        cpref[c * D + d] = p;
        p = carry[c * D + d] + b128 * p;
    }
}

// ================= router =================
__global__ void router_kernel(const float* __restrict__ h, const float* __restrict__ Wr2,
                              const float* __restrict__ br2, float* __restrict__ lam) {
    int t = blockIdx.x * (blockDim.x >> 5) + (threadIdx.x >> 5);
    int lane = threadIdx.x & 31;
    if (t >= T) return;
    const float* hp = h + (size_t)t * DH;
    float z0 = 0.f, z1 = 0.f;
    for (int i = lane; i < DH; i += 32) {
        float hv = hp[i];
        z0 += hv * Wr2[i * 2 + 0];
        z1 += hv * Wr2[i * 2 + 1];
    }
    #pragma unroll
    for (int off = 16; off; off >>= 1) {
        z0 += __shfl_xor_sync(0xffffffffu, z0, off);
        z1 += __shfl_xor_sync(0xffffffffu, z1, off);
    }
    if (lane == 0) {
        z0 += br2[0]; z1 += br2[1];
        float mx = fmaxf(z0, z1);
        float e0 = expf(z0 - mx), e1 = expf(z1 - mx);
        float inv = 1.f / (e0 + e1);
        lam[t * 2 + 0] = e0 * inv;
        lam[t * 2 + 1] = e1 * inv;
    }
}

// ====== fuse (EMA fixup) -> bf16 hi/lo directly ======
__global__ void fuse_hilo(const float* __restrict__ x, const float* __restrict__ l2,
                          const float* __restrict__ cpref, const float* __restrict__ lam,
                          __nv_bfloat16* __restrict__ fhi, __nv_bfloat16* __restrict__ flo) {
    int i = blockIdx.x * blockDim.x + threadIdx.x;
    if (i >= T * D / 2) return;
    int e = i * 2;
    int t = e >> 11, d = e & 2047;
    int c = t >> 7, tl = t & 127;
    const float LOGB = -0.10536051565f;
    float w = __expf((float)(tl + 1) * LOGB);
    float la = lam[t * 2], lb = lam[t * 2 + 1];
    float2 xv = *(const float2*)(x + e);
    float2 lv = *(const float2*)(l2 + e);
    float2 cp = *(const float2*)(cpref + c * D + d);
    float f0 = la * xv.x + lb * (lv.x + w * cp.x);
    float f1 = la * xv.y + lb * (lv.y + w * cp.y);
    uint32_t hw, lw;
    hilo2(f0, f1, hw, lw);
    ((uint32_t*)fhi)[i] = hw;
    ((uint32_t*)flo)[i] = lw;
}

// ================= RoPE -> bf16 hi/lo =================
__global__ void rope_hilo(const float* __restrict__ x, __nv_bfloat16* __restrict__ hi,
                          __nv_bfloat16* __restrict__ lo, int heads) {
    int idx = blockIdx.x * blockDim.x + threadIdx.x;
    int total = T * heads * 32;
    if (idx >= total) return;
    int jp = idx & 31;
    int hh = (idx >> 5) % heads;
    int t = idx / (heads * 32);
    int j = jp * 2;
    const float LN = 0.1439115683121279f;  // ln(10000)/64
    float inv0 = expf(-LN * j), inv1 = expf(-LN * (j + 1));
    float c0, s0, c1, s1;
    sincosf((float)t * inv0, &s0, &c0);
    sincosf((float)t * inv1, &s1, &c1);
    size_t base = (size_t)t * heads * HD + hh * HD;
    const float* p = x + base;
    float a0 = p[j], a1 = p[j + 1], b0 = p[j + 64], b1 = p[j + 65];
    float lo0 = a0 * c0 - b0 * s0, lo1 = a1 * c1 - b1 * s1;
    float up0 = b0 * c0 + a0 * s0, up1 = b1 * c1 + a1 * s1;
    uint32_t hw, lw;
    hilo2(lo0, lo1, hw, lw);
    *(uint32_t*)(hi + base + j) = hw;
    *(uint32_t*)(lo + base + j) = lw;
    hilo2(up0, up1, hw, lw);
    *(uint32_t*)(hi + base + j + 64) = hw;
    *(uint32_t*)(lo + base + j + 64) = lw;
}

// ================= tensor-core flash attention (256 thr, 128-row Q tile) =========
#define FA_STR 272
#define FA_QS 34816     // Q split size (128 rows)
#define FA_KS 17408     // KV split size (64 rows)
#define FA_KVB 69632
#define FA_KV0 69632
#define FA_SMEM 208896

__global__ __launch_bounds__(256, 1)
void fattn_kernel(const __nv_bfloat16* __restrict__ Qhi, const __nv_bfloat16* __restrict__ Qlo,
                  const __nv_bfloat16* __restrict__ Khi, const __nv_bfloat16* __restrict__ Klo,
                  const __nv_bfloat16* __restrict__ Vhi, const __nv_bfloat16* __restrict__ Vlo,
                  __nv_bfloat16* __restrict__ aoHi, __nv_bfloat16* __restrict__ aoLo) {
    extern __shared__ char smem[];
    const int tid = threadIdx.x, wid = tid >> 5, lane = tid & 31;
    const int qt = (int)(gridDim.x - 1 - blockIdx.x);   // long CTAs first
    const int head = blockIdx.y;
    const int kvh = head >> 2;
    const uint32_t sb = smem_u32(smem);
    const int g = lane >> 2, tq = lane & 3;
    const uint32_t lrow = lane & 15, lcol = (lane >> 4) * 16;

    // ---- Q tile fill: 128 rows hi/lo ----
    {
        const size_t qoff = (size_t)(qt * 128) * D + head * HD;
        const size_t dQ = (size_t)(Qlo - Qhi);
        #pragma unroll
        for (int i = 0; i < 8; i++) {
            int idx = tid + i * 256;
            int r = idx >> 4, c = idx & 15;
            const __nv_bfloat16* src = Qhi + qoff + (size_t)r * D + c * 8;
            uint32_t dst = sb + r * FA_STR + c * 16;
            CP16(dst, src);
            CP16(dst + FA_QS, src + dQ);
        }
        CP_COMMIT();
    }

    const int kts = 2 * qt + 2;
    const size_t dK = (size_t)(Klo - Khi), dV = (size_t)(Vlo - Vhi);
    auto loadKV = [&](int kt) {
        const size_t koff = (size_t)(kt * 64) * KVD + kvh * HD;
        const uint32_t kb = sb + FA_KV0 + (kt & 1) * FA_KVB;
        #pragma unroll
        for (int i = 0; i < 4; i++) {
            int idx = tid + i * 256;
            int r = idx >> 4, c = idx & 15;
            size_t so = koff + (size_t)r * KVD + c * 8;
            uint32_t dst = kb + r * FA_STR + c * 16;
            CP16(dst,              Khi + so);
            CP16(dst + FA_KS,      Khi + so + dK);
            CP16(dst + 2 * FA_KS,  Vhi + so);
            CP16(dst + 3 * FA_KS,  Vhi + so + dV);
        }
        CP_COMMIT();
    };
    loadKV(0);

    float m0 = -1e30f, m1 = -1e30f, l0 = 0.f, l1 = 0.f;
    float oa[16][4] = {};
    const float SC2 = 0.08838834764831845f * 1.4426950408889634f;

    for (int kt = 0; kt < kts; kt++) {
        if (kt + 1 < kts) { loadKV(kt + 1); CP_WAIT(1); }
        else              { CP_WAIT(0); }
        __syncthreads();
        const uint32_t kb = sb + FA_KV0 + (kt & 1) * FA_KVB;

        // ---- S = Q @ K^T ----
        float s[8][4];
        #pragma unroll
        for (int nf = 0; nf < 8; nf++)
            s[nf][0] = s[nf][1] = s[nf][2] = s[nf][3] = 0.f;
        #pragma unroll
        for (int ks = 0; ks < 8; ks++) {
            uint32_t ahi[4], alo[4], bhi[4][4], blo[4][4];
            uint32_t ra = sb + (wid * 16 + lrow) * FA_STR + lcol + ks * 32;
            ldsm_x4(ahi, ra);
            ldsm_x4(alo, ra + FA_QS);
            #pragma unroll
            for (int bt = 0; bt < 4; bt++) {
                uint32_t rb = kb + (bt * 16 + lrow) * FA_STR + lcol + ks * 32;
                ldsm_x4(bhi[bt], rb);
                ldsm_x4(blo[bt], rb + FA_KS);
            }
            #pragma unroll
            for (int nf = 0; nf < 8; nf++)
                mma16816(s[nf], ahi, bhi[nf >> 1][nf & 1], bhi[nf >> 1][2 + (nf & 1)]);
            #pragma unroll
            for (int nf = 0; nf < 8; nf++)
                mma16816(s[nf], ahi, blo[nf >> 1][nf & 1], blo[nf >> 1][2 + (nf & 1)]);
            #pragma unroll
            for (int nf = 0; nf < 8; nf++)
                mma16816(s[nf], alo, bhi[nf >> 1][nf & 1], bhi[nf >> 1][2 + (nf & 1)]);
        }

        // ---- causal mask (last two KV tiles overlap the diagonal) ----
        if (kt >= kts - 2) {
            int rg = qt * 128 + wid * 16 + g;
            int kbase = kt * 64;
            #pragma unroll
            for (int nf = 0; nf < 8; nf++) {
                int cg = kbase + nf * 8 + tq * 2;
                if (cg > rg)         s[nf][0] = -1e30f;
                if (cg + 1 > rg)     s[nf][1] = -1e30f;
                if (cg > rg + 8)     s[nf][2] = -1e30f;
                if (cg + 1 > rg + 8) s[nf][3] = -1e30f;
            }
        }

        float mx0 = -1e30f, mx1 = -1e30f;
        #pragma unroll
        for (int nf = 0; nf < 8; nf++) {
            mx0 = fmaxf(mx0, fmaxf(s[nf][0], s[nf][1]));
            mx1 = fmaxf(mx1, fmaxf(s[nf][2], s[nf][3]));
        }
        mx0 = fmaxf(mx0, __shfl_xor_sync(0xffffffffu, mx0, 1));
        mx0 = fmaxf(mx0, __shfl_xor_sync(0xffffffffu, mx0, 2));
        mx1 = fmaxf(mx1, __shfl_xor_sync(0xffffffffu, mx1, 1));
        mx1 = fmaxf(mx1, __shfl_xor_sync(0xffffffffu, mx1, 2));
        float mn0 = fmaxf(m0, mx0), mn1 = fmaxf(m1, mx1);
        float corr0 = ex2((m0 - mn0) * SC2);
        float corr1 = ex2((m1 - mn1) * SC2);
        m0 = mn0; m1 = mn1;
        l0 *= corr0; l1 *= corr1;
        #pragma unroll
        for (int nf = 0; nf < 8; nf++) {
            s[nf][0] = ex2((s[nf][0] - m0) * SC2);
            s[nf][1] = ex2((s[nf][1] - m0) * SC2);
            s[nf][2] = ex2((s[nf][2] - m1) * SC2);
            s[nf][3] = ex2((s[nf][3] - m1) * SC2);
            l0 += s[nf][0] + s[nf][1];
            l1 += s[nf][2] + s[nf][3];
        }
        #pragma unroll
        for (int nf = 0; nf < 16; nf++) {
            oa[nf][0] *= corr0; oa[nf][1] *= corr0;
            oa[nf][2] *= corr1; oa[nf][3] *= corr1;
        }

        // ---- O += P @ V ----
        const uint32_t vb = kb + 2 * FA_KS;
        #pragma unroll
        for (int pk = 0; pk < 4; pk++) {
            uint32_t pahi[4], palo[4];
            hilo2(s[2 * pk][0],     s[2 * pk][1],     pahi[0], palo[0]);
            hilo2(s[2 * pk][2],     s[2 * pk][3],     pahi[1], palo[1]);
            hilo2(s[2 * pk + 1][0], s[2 * pk + 1][1], pahi[2], palo[2]);
            hilo2(s[2 * pk + 1][2], s[2 * pk + 1][3], pahi[3], palo[3]);
            #pragma unroll
            for (int nbp = 0; nbp < 4; nbp++) {
                int nb0 = 2 * nbp, nb1 = 2 * nbp + 1;
                uint32_t vh0[4], vl0[4], vh1[4], vl1[4];
                uint32_t va0 = vb + (pk * 16 + lrow) * FA_STR + nb0 * 32 + lcol;
                uint32_t va1 = vb + (pk * 16 + lrow) * FA_STR + nb1 * 32 + lcol;
                ldsm_x4_t(vh0, va0);
                ldsm_x4_t(vh1, va1);
                ldsm_x4_t(vl0, va0 + FA_KS);
                ldsm_x4_t(vl1, va1 + FA_KS);
                mma16816(oa[2 * nb0],     pahi, vh0[0], vh0[1]);
                mma16816(oa[2 * nb0 + 1], pahi, vh0[2], vh0[3]);
                mma16816(oa[2 * nb1],     pahi, vh1[0], vh1[1]);
                mma16816(oa[2 * nb1 + 1], pahi, vh1[2], vh1[3]);
                mma16816(oa[2 * nb0],     pahi, vl0[0], vl0[1]);
                mma16816(oa[2 * nb0 + 1], pahi, vl0[2], vl0[3]);
                mma16816(oa[2 * nb1],     pahi, vl1[0], vl1[1]);
                mma16816(oa[2 * nb1 + 1], pahi, vl1[2], vl1[3]);
                mma16816(oa[2 * nb0],     palo, vh0[0], vh0[1]);
                mma16816(oa[2 * nb0 + 1], palo, vh0[2], vh0[3]);
                mma16816(oa[2 * nb1],     palo, vh1[0], vh1[1]);
                mma16816(oa[2 * nb1 + 1], palo, vh1[2], vh1[3]);
            }
        }
        __syncthreads();
    }

    l0 += __shfl_xor_sync(0xffffffffu, l0, 1);
    l0 += __shfl_xor_sync(0xffffffffu, l0, 2);
    l1 += __shfl_xor_sync(0xffffffffu, l1, 1);
    l1 += __shfl_xor_sync(0xffffffffu, l1, 2);
    float inv0 = 1.f / l0, inv1 = 1.f / l1;
    int row0 = qt * 128 + wid * 16 + g;
    size_t base0 = (size_t)row0 * D + head * HD + tq * 2;
    size_t base1 = base0 + 8 * D;
    #pragma unroll
    for (int nf = 0; nf < 16; nf++) {
        uint32_t hw, lw;
        hilo2(oa[nf][0] * inv0, oa[nf][1] * inv0, hw, lw);
        *(uint32_t*)(aoHi + base0 + nf * 8) = hw;
        *(uint32_t*)(aoLo + base0 + nf * 8) = lw;
        hilo2(oa[nf][2] * inv1, oa[nf][3] * inv1, hw, lw);
        *(uint32_t*)(aoHi + base1 + nf * 8) = hw;
        *(uint32_t*)(aoLo + base1 + nf * 8) = lw;
    }
}

// ================= launcher =================
extern "C" void kernel_launch(void* const* d_in, const int* in_sizes, int n_in,
                              void* d_out, int out_size) {
    const float* hs  = (const float*)d_in[0];
    const float* Wq  = (const float*)d_in[1];
    const float* Wk  = (const float*)d_in[2];
    const float* Wv  = (const float*)d_in[3];
    const float* Wo  = (const float*)d_in[4];
    const float* Wr1 = (const float*)d_in[5];
    const float* br1 = (const float*)d_in[6];
    const float* Wr2 = (const float*)d_in[7];
    const float* br2 = (const float*)d_in[8];
    float* out = (float*)d_out;

    float* S;
    cudaGetSymbolAddress((void**)&S, g_scratch);
    float* q     = S;
    float* l2    = S + 4 * MEG;
    float* h     = S + 8 * MEG;
    float* kbuf  = S + 10 * MEG;
    float* vbuf  = S + 11 * MEG;
    float* lam   = S + 12 * MEG;
    float* carry = lam + 4096;
    float* cpref = carry + 32768;
    __nv_bfloat16* Ahi     = (__nv_bfloat16*)(S + 13 * MEG);  // hs hilo; reused as ao hilo
    __nv_bfloat16* Alo     = (__nv_bfloat16*)(S + 15 * MEG);
    __nv_bfloat16* qhi     = (__nv_bfloat16*)(S + 17 * MEG);
    __nv_bfloat16* qlo     = (__nv_bfloat16*)(S + 19 * MEG);
    __nv_bfloat16* fusedhi = (__nv_bfloat16*)(S + 21 * MEG);
    __nv_bfloat16* fusedlo = (__nv_bfloat16*)(S + 23 * MEG);
    __nv_bfloat16* Whi     = (__nv_bfloat16*)(S + 25 * MEG);
    __nv_bfloat16* Wlo     = (__nv_bfloat16*)(S + 27 * MEG);
    __nv_bfloat16* QrHi    = (__nv_bfloat16*)(S + 29 * MEG);
    __nv_bfloat16* QrLo    = (__nv_bfloat16*)(S + 31 * MEG);
    __nv_bfloat16* KrHi    = (__nv_bfloat16*)(S + 33 * MEG);
    __nv_bfloat16* KrLo    = (__nv_bfloat16*)(S + 33 * MEG + 512 * 1024);
    __nv_bfloat16* VHi     = (__nv_bfloat16*)(S + 34 * MEG);
    __nv_bfloat16* VLo     = (__nv_bfloat16*)(S + 34 * MEG + 512 * 1024);

    cudaFuncSetAttribute(gemm_mma<0>, cudaFuncAttributeMaxDynamicSharedMemorySize, SMEMB);
    cudaFuncSetAttribute(gemm_mma<1>, cudaFuncAttributeMaxDynamicSharedMemorySize, SMEMB);
    cudaFuncSetAttribute(fattn_kernel, cudaFuncAttributeMaxDynamicSharedMemorySize, FA_SMEM);

    // ---- q = hs @ Wq (emit fp32 q + q hilo) ----
    conv_a<<<(T * D / 4 + 255) / 256, 256>>>(hs, Ahi, Alo, T * D / 4);
    conv_wt<<<dim3(D / 32, D / 32), 256>>>(Wq, Whi, Wlo, D, D);
    gemm_mma<0><<<dim3(D / 128, T / 128, 1), 256, SMEMB>>>(
        Ahi, Alo, Whi, Wlo, nullptr, q, qhi, qlo, T, D, D,
        nullptr, nullptr, nullptr, nullptr, nullptr);

    // ---- EMA ----
    ema1_kernel<<<dim3(16, 8), 256>>>(hs, l2, carry);
    ema2_kernel<<<8, 256>>>(carry, cpref);

    // ---- h = silu(q @ Wr1 + br1) ----
    conv_wt<<<dim3(DH / 32, D / 32), 256>>>(Wr1, Whi, Wlo, D, DH);
    gemm_mma<1><<<dim3(DH / 128, T / 128, 1), 256, SMEMB>>>(
        qhi, qlo, Whi, Wlo, br1, h, nullptr, nullptr, T, DH, D,
        nullptr, nullptr, nullptr, nullptr, nullptr);

    // ---- lam; fused -> hilo directly ----
    router_kernel<<<T / 8, 256>>>(h, Wr2, br2, lam);
    fuse_hilo<<<(T * D / 2 + 255) / 256, 256>>>(hs, l2, cpref, lam, fusedhi, fusedlo);

    // ---- k = fused @ Wk (fp32), v = fused @ Wv (fp32 + hilo) ----
    __nv_bfloat16* WkHi = Whi;
    __nv_bfloat16* WkLo = Whi + KVD * D;
    __nv_bfloat16* WvHi = Wlo;
    __nv_bfloat16* WvLo = Wlo + KVD * D;
    conv_wt<<<dim3(KVD / 32, D / 32), 256>>>(Wk, WkHi, WkLo, D, KVD);
    conv_wt<<<dim3(KVD / 32, D / 32), 256>>>(Wv, WvHi, WvLo, D, KVD);
    gemm_mma<0><<<dim3(KVD / 128, T / 128, 2), 256, SMEMB>>>(
        fusedhi, fusedlo, WkHi, WkLo, nullptr, kbuf, nullptr, nullptr, T, KVD, D,
        WvHi, WvLo, vbuf, VHi, VLo);

    // ---- RoPE -> hilo directly ----
    rope_hilo<<<(T * NH * 32 + 255) / 256, 256>>>(q, QrHi, QrLo, NH);
    rope_hilo<<<(T * NKVH * 32 + 255) / 256, 256>>>(kbuf, KrHi, KrLo, NKVH);

    // ---- flash attention -> ao hilo directly ----
    fattn_kernel<<<dim3(T / 128, NH), 256, FA_SMEM>>>(
        QrHi, QrLo, KrHi, KrLo, VHi, VLo, Ahi, Alo);

    // ---- out = ao @ Wo ----
    conv_wt<<<dim3(D / 32, D / 32), 256>>>(Wo, Whi, Wlo, D, D);
    gemm_mma<0><<<dim3(D / 128, T / 128, 1), 256, SMEMB>>>(
        Ahi, Alo, Whi, Wlo, nullptr, out, nullptr, nullptr, T, D, D,
        nullptr, nullptr, nullptr, nullptr, nullptr);
}

// round 11
// speedup vs baseline: 1.4003x; 1.3983x over previous
#include <cuda_runtime.h>
#include <cuda_fp16.h>
#include <math.h>
#include <stdint.h>

#define T 2048
#define D 2048
#define NH 16
#define NKVH 4
#define HD 128
#define DH 1024
#define KVD 512
#define MEG (1024*1024)

__device__ float g_scratch[35 * MEG];

// ================= PTX helpers =================
__device__ __forceinline__ uint32_t smem_u32(const void* p) {
    uint32_t a;
    asm("{ .reg .u64 t; cvta.to.shared.u64 t, %1; cvt.u32.u64 %0, t; }" : "=r"(a) : "l"(p));
    return a;
}
#define CP16(s, g) asm volatile("cp.async.cg.shared.global [%0], [%1], 16;" \
    :: "r"(s), "l"(__cvta_generic_to_global(g)) : "memory")
#define CP_COMMIT() asm volatile("cp.async.commit_group;" ::: "memory")
#define CP_WAIT(n)  asm volatile("cp.async.wait_group %0;" :: "n"(n) : "memory")

__device__ __forceinline__ void ldsm_x4(uint32_t* r, uint32_t addr) {
    asm volatile("ldmatrix.sync.aligned.m8n8.x4.shared.b16 {%0,%1,%2,%3}, [%4];"
        : "=r"(r[0]), "=r"(r[1]), "=r"(r[2]), "=r"(r[3]) : "r"(addr));
}
__device__ __forceinline__ void ldsm_x4_t(uint32_t* r, uint32_t addr) {
    asm volatile("ldmatrix.sync.aligned.m8n8.x4.trans.shared.b16 {%0,%1,%2,%3}, [%4];"
        : "=r"(r[0]), "=r"(r[1]), "=r"(r[2]), "=r"(r[3]) : "r"(addr));
}
__device__ __forceinline__ void mma16816(float* d, const uint32_t* a, uint32_t b0, uint32_t b1) {
    asm volatile("mma.sync.aligned.m16n8k16.row.col.f32.f16.f16.f32 "
        "{%0,%1,%2,%3}, {%4,%5,%6,%7}, {%8,%9}, {%0,%1,%2,%3};"
        : "+f"(d[0]), "+f"(d[1]), "+f"(d[2]), "+f"(d[3])
        : "r"(a[0]), "r"(a[1]), "r"(a[2]), "r"(a[3]), "r"(b0), "r"(b1));
}
__device__ __forceinline__ float ex2(float x) {
    float y; asm("ex2.approx.ftz.f32 %0, %1;" : "=f"(y) : "f"(x)); return y;
}
// fp16 hi/lo split of a float pair
__device__ __forceinline__ void hilo2(float a, float b, uint32_t& hi, uint32_t& lo) {
    __half2 h = __floats2half2_rn(a, b);
    __half2 l = __floats2half2_rn(a - __low2float(h), b - __high2float(h));
    hi = *(uint32_t*)&h; lo = *(uint32_t*)&l;
}

// ================= convert: fp32 -> fp16 hi/lo =================
__global__ void conv_a(const float* __restrict__ A, __half* __restrict__ hi,
                       __half* __restrict__ lo, int n4) {
    int i = blockIdx.x * blockDim.x + threadIdx.x;
    if (i >= n4) return;
    float4 a = ((const float4*)A)[i];
    uint32_t h0, l0, h1, l1;
    hilo2(a.x, a.y, h0, l0);
    hilo2(a.z, a.w, h1, l1);
    ((uint32_t*)hi)[2 * i] = h0;  ((uint32_t*)hi)[2 * i + 1] = h1;
    ((uint32_t*)lo)[2 * i] = l0;  ((uint32_t*)lo)[2 * i + 1] = l1;
}

// ========== convert + transpose weights: W[K,N] -> Wt[N,K] single fp16 ==========
__global__ void conv_wt(const float* __restrict__ W, __half* __restrict__ Wt,
                        int Kd, int Nd) {
    __shared__ float tile[32][33];
    int nb = blockIdx.x * 32, kb = blockIdx.y * 32;
    int tx = threadIdx.x & 31, ty0 = threadIdx.x >> 5;
    #pragma unroll
    for (int i = 0; i < 4; i++)
        tile[ty0 + 8 * i][tx] = W[(size_t)(kb + ty0 + 8 * i) * Nd + nb + tx];
    __syncthreads();
    #pragma unroll
    for (int i = 0; i < 4; i++) {
        int r = ty0 + 8 * i;
        Wt[(size_t)(nb + r) * Kd + kb + tx] = __float2half_rn(tile[tx][r]);
    }
}

// ================= fp16 2-term HMMA GEMM: C = (Ah+Al) @ Bt =================
#define SM_STRIDE 80
#define SM_SPLIT 10240
#define SM_BUF 30720
#define SMEMB 61440

template<int ACT>
__global__ __launch_bounds__(256, 1)
void gemm_mma(const __half* __restrict__ Ahi, const __half* __restrict__ Alo,
              const __half* __restrict__ B,
              const float* __restrict__ bias, float* __restrict__ C,
              __half* __restrict__ Chi, __half* __restrict__ Clo,
              int M, int N, int K,
              const __half* B2, float* C2, __half* C2hi, __half* C2lo) {
    extern __shared__ char smem[];
    if (blockIdx.z) { B = B2; C = C2; Chi = C2hi; Clo = C2lo; }
    const int tid = threadIdx.x, wid = tid >> 5, lane = tid & 31;
    const int m0 = blockIdx.y * 128, n0 = blockIdx.x * 128;
    const int wm = wid >> 2, wn = wid & 3;
    const uint32_t sb = smem_u32(smem);

    const int r0c = tid >> 2, c0c = (tid & 3);
    const int r1c = (tid + 256) >> 2, c1c = (tid & 3);

    auto fill = [&](int buf, int kc) {
        const int k0 = kc << 5;
        const uint32_t s0 = sb + buf * SM_BUF;
        uint32_t so0 = r0c * SM_STRIDE + c0c * 16;
        uint32_t so1 = r1c * SM_STRIDE + c1c * 16;
        const __half* a0 = Ahi + (size_t)(m0 + r0c) * K + k0 + c0c * 8;
        const __half* a1 = Ahi + (size_t)(m0 + r1c) * K + k0 + c1c * 8;
        const __half* b0 = B + (size_t)(n0 + r0c) * K + k0 + c0c * 8;
        const __half* b1 = B + (size_t)(n0 + r1c) * K + k0 + c1c * 8;
        size_t dAL = (size_t)(Alo - Ahi);
        CP16(s0 + so0, a0); CP16(s0 + so1, a1);
        CP16(s0 + SM_SPLIT + so0, a0 + dAL); CP16(s0 + SM_SPLIT + so1, a1 + dAL);
        CP16(s0 + 2 * SM_SPLIT + so0, b0); CP16(s0 + 2 * SM_SPLIT + so1, b1);
        CP_COMMIT();
    };

    float acc[4][4][4] = {};
    const int KC = K >> 5;
    fill(0, 0);
    for (int kc = 0; kc < KC; kc++) {
        if (kc + 1 < KC) { fill((kc + 1) & 1, kc + 1); CP_WAIT(1); }
        else             { CP_WAIT(0); }
        __syncthreads();
        const uint32_t base = sb + (kc & 1) * SM_BUF;
        const uint32_t lrow = (lane & 15), lcol = (lane >> 4) * 16;
        #pragma unroll
        for (int kh = 0; kh < 2; kh++) {
            uint32_t ahi[4][4], alo[4][4], bf[2][4];
            #pragma unroll
            for (int mt = 0; mt < 4; mt++) {
                uint32_t ra = base + (wm * 64 + mt * 16 + lrow) * SM_STRIDE + kh * 32 + lcol;
                ldsm_x4(ahi[mt], ra);
                ldsm_x4(alo[mt], ra + SM_SPLIT);
            }
            #pragma unroll
            for (int nt = 0; nt < 2; nt++) {
                uint32_t rb = base + 2 * SM_SPLIT + (wn * 32 + nt * 16 + lrow) * SM_STRIDE + kh * 32 + lcol;
                ldsm_x4(bf[nt], rb);
            }
            #pragma unroll
            for (int mt = 0; mt < 4; mt++)
                #pragma unroll
                for (int j = 0; j < 4; j++)
                    mma16816(acc[mt][j], ahi[mt], bf[j >> 1][j & 1], bf[j >> 1][2 + (j & 1)]);
            #pragma unroll
            for (int mt = 0; mt < 4; mt++)
                #pragma unroll
                for (int j = 0; j < 4; j++)
                    mma16816(acc[mt][j], alo[mt], bf[j >> 1][j & 1], bf[j >> 1][2 + (j & 1)]);
        }
        __syncthreads();
    }

    const int erow = m0 + wm * 64 + (lane >> 2);
    const int ecol = n0 + wn * 32 + (lane & 3) * 2;
    #pragma unroll
    for (int mt = 0; mt < 4; mt++)
        #pragma unroll
        for (int j = 0; j < 4; j++) {
            int r = erow + mt * 16, c = ecol + j * 8;
            float v0 = acc[mt][j][0], v1 = acc[mt][j][1];
            float v2 = acc[mt][j][2], v3 = acc[mt][j][3];
            if (ACT) {
                float b0 = bias[c], b1 = bias[c + 1];
                v0 += b0; v1 += b1; v2 += b0; v3 += b1;
                v0 = v0 / (1.f + expf(-v0)); v1 = v1 / (1.f + expf(-v1));
                v2 = v2 / (1.f + expf(-v2)); v3 = v3 / (1.f + expf(-v3));
            }
            *(float2*)(C + (size_t)r * N + c)       = make_float2(v0, v1);
            *(float2*)(C + (size_t)(r + 8) * N + c) = make_float2(v2, v3);
            if (Chi) {
                uint32_t hw, lw;
                hilo2(v0, v1, hw, lw);
                *(uint32_t*)(Chi + (size_t)r * N + c) = hw;
                if (Clo) *(uint32_t*)(Clo + (size_t)r * N + c) = lw;
                hilo2(v2, v3, hw, lw);
                *(uint32_t*)(Chi + (size_t)(r + 8) * N + c) = hw;
                if (Clo) *(uint32_t*)(Clo + (size_t)(r + 8) * N + c) = lw;
            }
        }
}

// ================= chunked causal EMA =================
__global__ void ema1_kernel(const float* __restrict__ x, float* __restrict__ l2,
                            float* __restrict__ carry) {
    int c = blockIdx.x;
    int d = blockIdx.y * 256 + threadIdx.x;
    const float beta = 0.9f, om = 0.1f;
    float m = 0.f;
    int t0 = c * 128;
    for (int t = t0; t < t0 + 128; t++) {
        m = beta * m + om * x[(size_t)t * D + d];
        l2[(size_t)t * D + d] = m;
    }
    carry[c * D + d] = m;
}
__global__ void ema2_kernel(const float* __restrict__ carry, float* __restrict__ cpref) {
    int d = blockIdx.x * 256 + threadIdx.x;
    const float b128 = 1.3900845e-06f;  // 0.9^128
    float p = 0.f;
    #pragma unroll
    for (int c = 0; c < 16; c++) {
        cpref[c * D + d] = p;
        p = carry[c * D + d] + b128 * p;
    }
}

// ================= router =================
__global__ void router_kernel(const float* __restrict__ h, const float* __restrict__ Wr2,
                              const float* __restrict__ br2, float* __restrict__ lam) {
    int t = blockIdx.x * (blockDim.x >> 5) + (threadIdx.x >> 5);
    int lane = threadIdx.x & 31;
    if (t >= T) return;
    const float* hp = h + (size_t)t * DH;
    float z0 = 0.f, z1 = 0.f;
    for (int i = lane; i < DH; i += 32) {
        float hv = hp[i];
        z0 += hv * Wr2[i * 2 + 0];
        z1 += hv * Wr2[i * 2 + 1];
    }
    #pragma unroll
    for (int off = 16; off; off >>= 1) {
        z0 += __shfl_xor_sync(0xffffffffu, z0, off);
        z1 += __shfl_xor_sync(0xffffffffu, z1, off);
    }
    if (lane == 0) {
        z0 += br2[0]; z1 += br2[1];
        float mx = fmaxf(z0, z1);
        float e0 = expf(z0 - mx), e1 = expf(z1 - mx);
        float inv = 1.f / (e0 + e1);
        lam[t * 2 + 0] = e0 * inv;
        lam[t * 2 + 1] = e1 * inv;
    }
}

// ====== fuse (EMA fixup) -> fp16 hi/lo directly ======
__global__ void fuse_hilo(const float* __restrict__ x, const float* __restrict__ l2,
                          const float* __restrict__ cpref, const float* __restrict__ lam,
                          __half* __restrict__ fhi, __half* __restrict__ flo) {
    int i = blockIdx.x * blockDim.x + threadIdx.x;
    if (i >= T * D / 2) return;
    int e = i * 2;
    int t = e >> 11, d = e & 2047;
    int c = t >> 7, tl = t & 127;
    const float LOGB = -0.10536051565f;
    float w = __expf((float)(tl + 1) * LOGB);
    float la = lam[t * 2], lb = lam[t * 2 + 1];
    float2 xv = *(const float2*)(x + e);
    float2 lv = *(const float2*)(l2 + e);
    float2 cp = *(const float2*)(cpref + c * D + d);
    float f0 = la * xv.x + lb * (lv.x + w * cp.x);
    float f1 = la * xv.y + lb * (lv.y + w * cp.y);
    uint32_t hw, lw;
    hilo2(f0, f1, hw, lw);
    ((uint32_t*)fhi)[i] = hw;
    ((uint32_t*)flo)[i] = lw;
}

// ================= RoPE -> fp16 hi/lo (lo optional) =================
__global__ void rope_hilo(const float* __restrict__ x, __half* __restrict__ hi,
                          __half* __restrict__ lo, int heads) {
    int idx = blockIdx.x * blockDim.x + threadIdx.x;
    int total = T * heads * 32;
    if (idx >= total) return;
    int jp = idx & 31;
    int hh = (idx >> 5) % heads;
    int t = idx / (heads * 32);
    int j = jp * 2;
    const float LN = 0.1439115683121279f;  // ln(10000)/64
    float inv0 = expf(-LN * j), inv1 = expf(-LN * (j + 1));
    float c0, s0, c1, s1;
    sincosf((float)t * inv0, &s0, &c0);
    sincosf((float)t * inv1, &s1, &c1);
    size_t base = (size_t)t * heads * HD + hh * HD;
    const float* p = x + base;
    float a0 = p[j], a1 = p[j + 1], b0 = p[j + 64], b1 = p[j + 65];
    float lo0 = a0 * c0 - b0 * s0, lo1 = a1 * c1 - b1 * s1;
    float up0 = b0 * c0 + a0 * s0, up1 = b1 * c1 + a1 * s1;
    uint32_t hw, lw;
    hilo2(lo0, lo1, hw, lw);
    *(uint32_t*)(hi + base + j) = hw;
    if (lo) *(uint32_t*)(lo + base + j) = lw;
    hilo2(up0, up1, hw, lw);
    *(uint32_t*)(hi + base + j + 64) = hw;
    if (lo) *(uint32_t*)(lo + base + j + 64) = lw;
}

// ===== tensor-core flash attention (256 thr, 128-row Q tile, fp16 2-term) =====
// SMEM: Qhi 0, Qlo 34816, KV buffers at 69632 + buf*34816: [K 0, V 17408]
#define FA_STR 272
#define FA_QS 34816
#define FA_KS 17408
#define FA_KVB 34816
#define FA_KV0 69632
#define FA_SMEM 139264

__global__ __launch_bounds__(256, 1)
void fattn_kernel(const __half* __restrict__ Qhi, const __half* __restrict__ Qlo,
                  const __half* __restrict__ Khi, const __half* __restrict__ Vhi,
                  __half* __restrict__ aoHi, __half* __restrict__ aoLo) {
    extern __shared__ char smem[];
    const int tid = threadIdx.x, wid = tid >> 5, lane = tid & 31;
    const int qt = (int)(gridDim.x - 1 - blockIdx.x);   // long CTAs first
    const int head = blockIdx.y;
    const int kvh = head >> 2;
    const uint32_t sb = smem_u32(smem);
    const int g = lane >> 2, tq = lane & 3;
    const uint32_t lrow = lane & 15, lcol = (lane >> 4) * 16;

    // ---- Q tile fill: 128 rows hi/lo ----
    {
        const size_t qoff = (size_t)(qt * 128) * D + head * HD;
        const size_t dQ = (size_t)(Qlo - Qhi);
        #pragma unroll
        for (int i = 0; i < 8; i++) {
            int idx = tid + i * 256;
            int r = idx >> 4, c = idx & 15;
            const __half* src = Qhi + qoff + (size_t)r * D + c * 8;
            uint32_t dst = sb + r * FA_STR + c * 16;
            CP16(dst, src);
            CP16(dst + FA_QS, src + dQ);
        }
        CP_COMMIT();
    }

    const int kts = 2 * qt + 2;
    auto loadKV = [&](int kt) {
        const size_t koff = (size_t)(kt * 64) * KVD + kvh * HD;
        const uint32_t kb = sb + FA_KV0 + (kt & 1) * FA_KVB;
        #pragma unroll
        for (int i = 0; i < 4; i++) {
            int idx = tid + i * 256;
            int r = idx >> 4, c = idx & 15;
            size_t so = koff + (size_t)r * KVD + c * 8;
            uint32_t dst = kb + r * FA_STR + c * 16;
            CP16(dst,         Khi + so);
            CP16(dst + FA_KS, Vhi + so);
        }
        CP_COMMIT();
    };
    loadKV(0);

    float m0 = -1e30f, m1 = -1e30f, l0 = 0.f, l1 = 0.f;
    float oa[16][4] = {};
    const float SC2 = 0.08838834764831845f * 1.4426950408889634f;

    for (int kt = 0; kt < kts; kt++) {
        if (kt + 1 < kts) { loadKV(kt + 1); CP_WAIT(1); }
        else              { CP_WAIT(0); }
        __syncthreads();
        const uint32_t kb = sb + FA_KV0 + (kt & 1) * FA_KVB;

        // ---- S = Q @ K^T (Qhi·K then Qlo·K) ----
        float s[8][4];
        #pragma unroll
        for (int nf = 0; nf < 8; nf++)
            s[nf][0] = s[nf][1] = s[nf][2] = s[nf][3] = 0.f;
        #pragma unroll
        for (int ks = 0; ks < 8; ks++) {
            uint32_t ahi[4], alo[4], bk[4][4];
            uint32_t ra = sb + (wid * 16 + lrow) * FA_STR + lcol + ks * 32;
            ldsm_x4(ahi, ra);
            ldsm_x4(alo, ra + FA_QS);
            #pragma unroll
            for (int bt = 0; bt < 4; bt++) {
                uint32_t rb = kb + (bt * 16 + lrow) * FA_STR + lcol + ks * 32;
                ldsm_x4(bk[bt], rb);
            }
            #pragma unroll
            for (int nf = 0; nf < 8; nf++)
                mma16816(s[nf], ahi, bk[nf >> 1][nf & 1], bk[nf >> 1][2 + (nf & 1)]);
            #pragma unroll
            for (int nf = 0; nf < 8; nf++)
                mma16816(s[nf], alo, bk[nf >> 1][nf & 1], bk[nf >> 1][2 + (nf & 1)]);
        }

        // ---- causal mask (last two KV tiles overlap the diagonal) ----
        if (kt >= kts - 2) {
            int rg = qt * 128 + wid * 16 + g;
            int kbase = kt * 64;
            #pragma unroll
            for (int nf = 0; nf < 8; nf++) {
                int cg = kbase + nf * 8 + tq * 2;
                if (cg > rg)         s[nf][0] = -1e30f;
                if (cg + 1 > rg)     s[nf][1] = -1e30f;
                if (cg > rg + 8)     s[nf][2] = -1e30f;
                if (cg + 1 > rg + 8) s[nf][3] = -1e30f;
            }
        }

        float mx0 = -1e30f, mx1 = -1e30f;
        #pragma unroll
        for (int nf = 0; nf < 8; nf++) {
            mx0 = fmaxf(mx0, fmaxf(s[nf][0], s[nf][1]));
            mx1 = fmaxf(mx1, fmaxf(s[nf][2], s[nf][3]));
        }
        mx0 = fmaxf(mx0, __shfl_xor_sync(0xffffffffu, mx0, 1));
        mx0 = fmaxf(mx0, __shfl_xor_sync(0xffffffffu, mx0, 2));
        mx1 = fmaxf(mx1, __shfl_xor_sync(0xffffffffu, mx1, 1));
        mx1 = fmaxf(mx1, __shfl_xor_sync(0xffffffffu, mx1, 2));
        float mn0 = fmaxf(m0, mx0), mn1 = fmaxf(m1, mx1);
        float corr0 = ex2((m0 - mn0) * SC2);
        float corr1 = ex2((m1 - mn1) * SC2);
        m0 = mn0; m1 = mn1;
        l0 *= corr0; l1 *= corr1;
        #pragma unroll
        for (int nf = 0; nf < 8; nf++) {
            s[nf][0] = ex2((s[nf][0] - m0) * SC2);
            s[nf][1] = ex2((s[nf][1] - m0) * SC2);
            s[nf][2] = ex2((s[nf][2] - m1) * SC2);
            s[nf][3] = ex2((s[nf][3] - m1) * SC2);
            l0 += s[nf][0] + s[nf][1];
            l1 += s[nf][2] + s[nf][3];
        }
        #pragma unroll
        for (int nf = 0; nf < 16; nf++) {
            oa[nf][0] *= corr0; oa[nf][1] *= corr0;
            oa[nf][2] *= corr1; oa[nf][3] *= corr1;
        }

        // ---- O += P @ V (P hi/lo in regs, V single) ----
        const uint32_t vb = kb + FA_KS;
        #pragma unroll
        for (int pk = 0; pk < 4; pk++) {
            uint32_t pahi[4], palo[4];
            hilo2(s[2 * pk][0],     s[2 * pk][1],     pahi[0], palo[0]);
            hilo2(s[2 * pk][2],     s[2 * pk][3],     pahi[1], palo[1]);
            hilo2(s[2 * pk + 1][0], s[2 * pk + 1][1], pahi[2], palo[2]);
            hilo2(s[2 * pk + 1][2], s[2 * pk + 1][3], pahi[3], palo[3]);
            #pragma unroll
            for (int nbp = 0; nbp < 4; nbp++) {
                int nb0 = 2 * nbp, nb1 = 2 * nbp + 1;
                uint32_t vh0[4], vh1[4];
                uint32_t va0 = vb + (pk * 16 + lrow) * FA_STR + nb0 * 32 + lcol;
                uint32_t va1 = vb + (pk * 16 + lrow) * FA_STR + nb1 * 32 + lcol;
                ldsm_x4_t(vh0, va0);
                ldsm_x4_t(vh1, va1);
                mma16816(oa[2 * nb0],     pahi, vh0[0], vh0[1]);
                mma16816(oa[2 * nb0 + 1], pahi, vh0[2], vh0[3]);
                mma16816(oa[2 * nb1],     pahi, vh1[0], vh1[1]);
                mma16816(oa[2 * nb1 + 1], pahi, vh1[2], vh1[3]);
                mma16816(oa[2 * nb0],     palo, vh0[0], vh0[1]);
                mma16816(oa[2 * nb0 + 1], palo, vh0[2], vh0[3]);
                mma16816(oa[2 * nb1],     palo, vh1[0], vh1[1]);
                mma16816(oa[2 * nb1 + 1], palo, vh1[2], vh1[3]);
            }
        }
        __syncthreads();
    }

    l0 += __shfl_xor_sync(0xffffffffu, l0, 1);
    l0 += __shfl_xor_sync(0xffffffffu, l0, 2);
    l1 += __shfl_xor_sync(0xffffffffu, l1, 1);
    l1 += __shfl_xor_sync(0xffffffffu, l1, 2);
    float inv0 = 1.f / l0, inv1 = 1.f / l1;
    int row0 = qt * 128 + wid * 16 + g;
    size_t base0 = (size_t)row0 * D + head * HD + tq * 2;
    size_t base1 = base0 + 8 * D;
    #pragma unroll
    for (int nf = 0; nf < 16; nf++) {
        uint32_t hw, lw;
        hilo2(oa[nf][0] * inv0, oa[nf][1] * inv0, hw, lw);
        *(uint32_t*)(aoHi + base0 + nf * 8) = hw;
        *(uint32_t*)(aoLo + base0 + nf * 8) = lw;
        hilo2(oa[nf][2] * inv1, oa[nf][3] * inv1, hw, lw);
        *(uint32_t*)(aoHi + base1 + nf * 8) = hw;
        *(uint32_t*)(aoLo + base1 + nf * 8) = lw;
    }
}

// ================= launcher =================
extern "C" void kernel_launch(void* const* d_in, const int* in_sizes, int n_in,
                              void* d_out, int out_size) {
    const float* hs  = (const float*)d_in[0];
    const float* Wq  = (const float*)d_in[1];
    const float* Wk  = (const float*)d_in[2];
    const float* Wv  = (const float*)d_in[3];
    const float* Wo  = (const float*)d_in[4];
    const float* Wr1 = (const float*)d_in[5];
    const float* br1 = (const float*)d_in[6];
    const float* Wr2 = (const float*)d_in[7];
    const float* br2 = (const float*)d_in[8];
    float* out = (float*)d_out;

    float* S;
    cudaGetSymbolAddress((void**)&S, g_scratch);
    float* q     = S;
    float* l2    = S + 4 * MEG;
    float* h     = S + 8 * MEG;
    float* kbuf  = S + 10 * MEG;
    float* vbuf  = S + 11 * MEG;
    float* lam   = S + 12 * MEG;
    float* carry = lam + 4096;
    float* cpref = carry + 32768;
    __half* Ahi     = (__half*)(S + 13 * MEG);  // hs hilo; reused as ao hilo
    __half* Alo     = (__half*)(S + 15 * MEG);
    __half* qhi     = (__half*)(S + 17 * MEG);
    __half* qlo     = (__half*)(S + 19 * MEG);
    __half* fusedhi = (__half*)(S + 21 * MEG);
    __half* fusedlo = (__half*)(S + 23 * MEG);
    __half* Wt      = (__half*)(S + 25 * MEG);  // transposed weight, single fp16
    __half* QrHi    = (__half*)(S + 29 * MEG);
    __half* QrLo    = (__half*)(S + 31 * MEG);
    __half* KrHi    = (__half*)(S + 33 * MEG);
    __half* VHi     = (__half*)(S + 34 * MEG);

    cudaFuncSetAttribute(gemm_mma<0>, cudaFuncAttributeMaxDynamicSharedMemorySize, SMEMB);
    cudaFuncSetAttribute(gemm_mma<1>, cudaFuncAttributeMaxDynamicSharedMemorySize, SMEMB);
    cudaFuncSetAttribute(fattn_kernel, cudaFuncAttributeMaxDynamicSharedMemorySize, FA_SMEM);

    // ---- q = hs @ Wq (emit fp32 q + q hilo) ----
    conv_a<<<(T * D / 4 + 255) / 256, 256>>>(hs, Ahi, Alo, T * D / 4);
    conv_wt<<<dim3(D / 32, D / 32), 256>>>(Wq, Wt, D, D);
    gemm_mma<0><<<dim3(D / 128, T / 128, 1), 256, SMEMB>>>(
        Ahi, Alo, Wt, nullptr, q, qhi, qlo, T, D, D,
        nullptr, nullptr, nullptr, nullptr);

    // ---- EMA ----
    ema1_kernel<<<dim3(16, 8), 256>>>(hs, l2, carry);
    ema2_kernel<<<8, 256>>>(carry, cpref);

    // ---- h = silu(q @ Wr1 + br1) ----
    conv_wt<<<dim3(DH / 32, D / 32), 256>>>(Wr1, Wt, D, DH);
    gemm_mma<1><<<dim3(DH / 128, T / 128, 1), 256, SMEMB>>>(
        qhi, qlo, Wt, br1, h, nullptr, nullptr, T, DH, D,
        nullptr, nullptr, nullptr, nullptr);

    // ---- lam; fused -> hilo directly ----
    router_kernel<<<T / 8, 256>>>(h, Wr2, br2, lam);
    fuse_hilo<<<(T * D / 2 + 255) / 256, 256>>>(hs, l2, cpref, lam, fusedhi, fusedlo);

    // ---- k = fused @ Wk (fp32), v = fused @ Wv (fp32 + single fp16) ----
    __half* WkT = Wt;
    __half* WvT = Wt + (size_t)KVD * D;
    conv_wt<<<dim3(KVD / 32, D / 32), 256>>>(Wk, WkT, D, KVD);
    conv_wt<<<dim3(KVD / 32, D / 32), 256>>>(Wv, WvT, D, KVD);
    gemm_mma<0><<<dim3(KVD / 128, T / 128, 2), 256, SMEMB>>>(
        fusedhi, fusedlo, WkT, nullptr, kbuf, nullptr, nullptr, T, KVD, D,
        WvT, vbuf, VHi, nullptr);

    // ---- RoPE: q -> hilo, k -> single ----
    rope_hilo<<<(T * NH * 32 + 255) / 256, 256>>>(q, QrHi, QrLo, NH);
    rope_hilo<<<(T * NKVH * 32 + 255) / 256, 256>>>(kbuf, KrHi, nullptr, NKVH);

    // ---- flash attention -> ao hilo directly ----
    fattn_kernel<<<dim3(T / 128, NH), 256, FA_SMEM>>>(
        QrHi, QrLo, KrHi, VHi, Ahi, Alo);

    // ---- out = ao @ Wo ----
    conv_wt<<<dim3(D / 32, D / 32), 256>>>(Wo, Wt, D, D);
    gemm_mma<0><<<dim3(D / 128, T / 128, 1), 256, SMEMB>>>(
        Ahi, Alo, Wt, nullptr, out, nullptr, nullptr, T, D, D,
        nullptr, nullptr, nullptr, nullptr);
}

// round 12
// speedup vs baseline: 2.2385x; 1.5986x over previous
#include <cuda_runtime.h>
#include <cuda_fp16.h>
#include <math.h>
#include <stdint.h>

#define T 2048
#define D 2048
#define NH 16
#define NKVH 4
#define HD 128
#define DH 1024
#define KVD 512
#define MEG (1024*1024)

__device__ float g_scratch[28 * MEG];

// ================= PTX helpers =================
__device__ __forceinline__ uint32_t smem_u32(const void* p) {
    uint32_t a;
    asm("{ .reg .u64 t; cvta.to.shared.u64 t, %1; cvt.u32.u64 %0, t; }" : "=r"(a) : "l"(p));
    return a;
}
#define CP16(s, g) asm volatile("cp.async.cg.shared.global [%0], [%1], 16;" \
    :: "r"(s), "l"(__cvta_generic_to_global(g)) : "memory")
#define CP_COMMIT() asm volatile("cp.async.commit_group;" ::: "memory")
#define CP_WAIT(n)  asm volatile("cp.async.wait_group %0;" :: "n"(n) : "memory")

__device__ __forceinline__ void ldsm_x4(uint32_t* r, uint32_t addr) {
    asm volatile("ldmatrix.sync.aligned.m8n8.x4.shared.b16 {%0,%1,%2,%3}, [%4];"
        : "=r"(r[0]), "=r"(r[1]), "=r"(r[2]), "=r"(r[3]) : "r"(addr));
}
__device__ __forceinline__ void ldsm_x4_t(uint32_t* r, uint32_t addr) {
    asm volatile("ldmatrix.sync.aligned.m8n8.x4.trans.shared.b16 {%0,%1,%2,%3}, [%4];"
        : "=r"(r[0]), "=r"(r[1]), "=r"(r[2]), "=r"(r[3]) : "r"(addr));
}
__device__ __forceinline__ void mma16816(float* d, const uint32_t* a, uint32_t b0, uint32_t b1) {
    asm volatile("mma.sync.aligned.m16n8k16.row.col.f32.f16.f16.f32 "
        "{%0,%1,%2,%3}, {%4,%5,%6,%7}, {%8,%9}, {%0,%1,%2,%3};"
        : "+f"(d[0]), "+f"(d[1]), "+f"(d[2]), "+f"(d[3])
        : "r"(a[0]), "r"(a[1]), "r"(a[2]), "r"(a[3]), "r"(b0), "r"(b1));
}
__device__ __forceinline__ float ex2(float x) {
    float y; asm("ex2.approx.ftz.f32 %0, %1;" : "=f"(y) : "f"(x)); return y;
}
__device__ __forceinline__ uint32_t pk2(float a, float b) {
    __half2 h = __floats2half2_rn(a, b);
    return *(uint32_t*)&h;
}

// ================= convert: fp32 -> fp16 =================
__global__ void conv_a(const float* __restrict__ A, __half* __restrict__ out, int n4) {
    int i = blockIdx.x * blockDim.x + threadIdx.x;
    if (i >= n4) return;
    float4 a = ((const float4*)A)[i];
    ((uint32_t*)out)[2 * i]     = pk2(a.x, a.y);
    ((uint32_t*)out)[2 * i + 1] = pk2(a.z, a.w);
}

// ========== convert + transpose weights: W[K,N] -> Wt[N,K] fp16 ==========
__global__ void conv_wt(const float* __restrict__ W, __half* __restrict__ Wt,
                        int Kd, int Nd) {
    __shared__ float tile[32][33];
    int nb = blockIdx.x * 32, kb = blockIdx.y * 32;
    int tx = threadIdx.x & 31, ty0 = threadIdx.x >> 5;
    #pragma unroll
    for (int i = 0; i < 4; i++)
        tile[ty0 + 8 * i][tx] = W[(size_t)(kb + ty0 + 8 * i) * Nd + nb + tx];
    __syncthreads();
    #pragma unroll
    for (int i = 0; i < 4; i++) {
        int r = ty0 + 8 * i;
        Wt[(size_t)(nb + r) * Kd + kb + tx] = __float2half_rn(tile[tx][r]);
    }
}

// ================= fp16 HMMA GEMM: C = A @ Bt =================
#define SM_STRIDE 80
#define SM_SPLIT 10240
#define SM_BUF 20480
#define SMEMB 40960

template<int ACT>
__global__ __launch_bounds__(256, 1)
void gemm_mma(const __half* __restrict__ A, const __half* __restrict__ B,
              const float* __restrict__ bias, float* __restrict__ C,
              __half* __restrict__ Chi,
              int M, int N, int K,
              const __half* B2, float* C2, __half* C2hi) {
    extern __shared__ char smem[];
    if (blockIdx.z) { B = B2; C = C2; Chi = C2hi; }
    const int tid = threadIdx.x, wid = tid >> 5, lane = tid & 31;
    const int m0 = blockIdx.y * 128, n0 = blockIdx.x * 128;
    const int wm = wid >> 2, wn = wid & 3;
    const uint32_t sb = smem_u32(smem);

    const int r0c = tid >> 2, c0c = (tid & 3);
    const int r1c = (tid + 256) >> 2, c1c = (tid & 3);

    auto fill = [&](int buf, int kc) {
        const int k0 = kc << 5;
        const uint32_t s0 = sb + buf * SM_BUF;
        uint32_t so0 = r0c * SM_STRIDE + c0c * 16;
        uint32_t so1 = r1c * SM_STRIDE + c1c * 16;
        CP16(s0 + so0, A + (size_t)(m0 + r0c) * K + k0 + c0c * 8);
        CP16(s0 + so1, A + (size_t)(m0 + r1c) * K + k0 + c1c * 8);
        CP16(s0 + SM_SPLIT + so0, B + (size_t)(n0 + r0c) * K + k0 + c0c * 8);
        CP16(s0 + SM_SPLIT + so1, B + (size_t)(n0 + r1c) * K + k0 + c1c * 8);
        CP_COMMIT();
    };

    float acc[4][4][4] = {};
    const int KC = K >> 5;
    fill(0, 0);
    for (int kc = 0; kc < KC; kc++) {
        if (kc + 1 < KC) { fill((kc + 1) & 1, kc + 1); CP_WAIT(1); }
        else             { CP_WAIT(0); }
        __syncthreads();
        const uint32_t base = sb + (kc & 1) * SM_BUF;
        const uint32_t lrow = (lane & 15), lcol = (lane >> 4) * 16;
        #pragma unroll
        for (int kh = 0; kh < 2; kh++) {
            uint32_t af[4][4], bf[2][4];
            #pragma unroll
            for (int mt = 0; mt < 4; mt++) {
                uint32_t ra = base + (wm * 64 + mt * 16 + lrow) * SM_STRIDE + kh * 32 + lcol;
                ldsm_x4(af[mt], ra);
            }
            #pragma unroll
            for (int nt = 0; nt < 2; nt++) {
                uint32_t rb = base + SM_SPLIT + (wn * 32 + nt * 16 + lrow) * SM_STRIDE + kh * 32 + lcol;
                ldsm_x4(bf[nt], rb);
            }
            #pragma unroll
            for (int mt = 0; mt < 4; mt++)
                #pragma unroll
                for (int j = 0; j < 4; j++)
                    mma16816(acc[mt][j], af[mt], bf[j >> 1][j & 1], bf[j >> 1][2 + (j & 1)]);
        }
        __syncthreads();
    }

    const int erow = m0 + wm * 64 + (lane >> 2);
    const int ecol = n0 + wn * 32 + (lane & 3) * 2;
    #pragma unroll
    for (int mt = 0; mt < 4; mt++)
        #pragma unroll
        for (int j = 0; j < 4; j++) {
            int r = erow + mt * 16, c = ecol + j * 8;
            float v0 = acc[mt][j][0], v1 = acc[mt][j][1];
            float v2 = acc[mt][j][2], v3 = acc[mt][j][3];
            if (ACT) {
                float b0 = bias[c], b1 = bias[c + 1];
                v0 += b0; v1 += b1; v2 += b0; v3 += b1;
                v0 = v0 / (1.f + expf(-v0)); v1 = v1 / (1.f + expf(-v1));
                v2 = v2 / (1.f + expf(-v2)); v3 = v3 / (1.f + expf(-v3));
            }
            *(float2*)(C + (size_t)r * N + c)       = make_float2(v0, v1);
            *(float2*)(C + (size_t)(r + 8) * N + c) = make_float2(v2, v3);
            if (Chi) {
                *(uint32_t*)(Chi + (size_t)r * N + c)       = pk2(v0, v1);
                *(uint32_t*)(Chi + (size_t)(r + 8) * N + c) = pk2(v2, v3);
            }
        }
}

// ================= chunked causal EMA =================
__global__ void ema1_kernel(const float* __restrict__ x, float* __restrict__ l2,
                            float* __restrict__ carry) {
    int c = blockIdx.x;
    int d = blockIdx.y * 256 + threadIdx.x;
    const float beta = 0.9f, om = 0.1f;
    float m = 0.f;
    int t0 = c * 128;
    for (int t = t0; t < t0 + 128; t++) {
        m = beta * m + om * x[(size_t)t * D + d];
        l2[(size_t)t * D + d] = m;
    }
    carry[c * D + d] = m;
}
__global__ void ema2_kernel(const float* __restrict__ carry, float* __restrict__ cpref) {
    int d = blockIdx.x * 256 + threadIdx.x;
    const float b128 = 1.3900845e-06f;  // 0.9^128
    float p = 0.f;
    #pragma unroll
    for (int c = 0; c < 16; c++) {
        cpref[c * D + d] = p;
        p = carry[c * D + d] + b128 * p;
    }
}

// ================= router =================
__global__ void router_kernel(const float* __restrict__ h, const float* __restrict__ Wr2,
                              const float* __restrict__ br2, float* __restrict__ lam) {
    int t = blockIdx.x * (blockDim.x >> 5) + (threadIdx.x >> 5);
    int lane = threadIdx.x & 31;
    if (t >= T) return;
    const float* hp = h + (size_t)t * DH;
    float z0 = 0.f, z1 = 0.f;
    for (int i = lane; i < DH; i += 32) {
        float hv = hp[i];
        z0 += hv * Wr2[i * 2 + 0];
        z1 += hv * Wr2[i * 2 + 1];
    }
    #pragma unroll
    for (int off = 16; off; off >>= 1) {
        z0 += __shfl_xor_sync(0xffffffffu, z0, off);
        z1 += __shfl_xor_sync(0xffffffffu, z1, off);
    }
    if (lane == 0) {
        z0 += br2[0]; z1 += br2[1];
        float mx = fmaxf(z0, z1);
        float e0 = expf(z0 - mx), e1 = expf(z1 - mx);
        float inv = 1.f / (e0 + e1);
        lam[t * 2 + 0] = e0 * inv;
        lam[t * 2 + 1] = e1 * inv;
    }
}

// ====== fuse (EMA fixup) -> fp16 directly ======
__global__ void fuse_h(const float* __restrict__ x, const float* __restrict__ l2,
                       const float* __restrict__ cpref, const float* __restrict__ lam,
                       __half* __restrict__ fh) {
    int i = blockIdx.x * blockDim.x + threadIdx.x;
    if (i >= T * D / 2) return;
    int e = i * 2;
    int t = e >> 11, d = e & 2047;
    int c = t >> 7, tl = t & 127;
    const float LOGB = -0.10536051565f;
    float w = __expf((float)(tl + 1) * LOGB);
    float la = lam[t * 2], lb = lam[t * 2 + 1];
    float2 xv = *(const float2*)(x + e);
    float2 lv = *(const float2*)(l2 + e);
    float2 cp = *(const float2*)(cpref + c * D + d);
    float f0 = la * xv.x + lb * (lv.x + w * cp.x);
    float f1 = la * xv.y + lb * (lv.y + w * cp.y);
    ((uint32_t*)fh)[i] = pk2(f0, f1);
}

// ================= RoPE -> fp16 =================
__global__ void rope_h(const float* __restrict__ x, __half* __restrict__ hi, int heads) {
    int idx = blockIdx.x * blockDim.x + threadIdx.x;
    int total = T * heads * 32;
    if (idx >= total) return;
    int jp = idx & 31;
    int hh = (idx >> 5) % heads;
    int t = idx / (heads * 32);
    int j = jp * 2;
    const float LN = 0.1439115683121279f;  // ln(10000)/64
    float inv0 = expf(-LN * j), inv1 = expf(-LN * (j + 1));
    float c0, s0, c1, s1;
    sincosf((float)t * inv0, &s0, &c0);
    sincosf((float)t * inv1, &s1, &c1);
    size_t base = (size_t)t * heads * HD + hh * HD;
    const float* p = x + base;
    float a0 = p[j], a1 = p[j + 1], b0 = p[j + 64], b1 = p[j + 65];
    *(uint32_t*)(hi + base + j)      = pk2(a0 * c0 - b0 * s0, a1 * c1 - b1 * s1);
    *(uint32_t*)(hi + base + j + 64) = pk2(b0 * c0 + a0 * s0, b1 * c1 + a1 * s1);
}

// ===== tensor-core flash attention (256 thr, 128-row Q tile, pure fp16) =====
// SMEM: Q 0..34816, KV buffers at 34816 + buf*34816: [K 0, V 17408]
#define FA_STR 272
#define FA_QS 34816
#define FA_KS 17408
#define FA_KVB 34816
#define FA_KV0 34816
#define FA_SMEM 104448

__global__ __launch_bounds__(256, 1)
void fattn_kernel(const __half* __restrict__ Q, const __half* __restrict__ K,
                  const __half* __restrict__ V, __half* __restrict__ aoH) {
    extern __shared__ char smem[];
    const int tid = threadIdx.x, wid = tid >> 5, lane = tid & 31;
    const int qt = (int)(gridDim.x - 1 - blockIdx.x);   // long CTAs first
    const int head = blockIdx.y;
    const int kvh = head >> 2;
    const uint32_t sb = smem_u32(smem);
    const int g = lane >> 2, tq = lane & 3;
    const uint32_t lrow = lane & 15, lcol = (lane >> 4) * 16;

    // ---- Q tile fill: 128 rows ----
    {
        const size_t qoff = (size_t)(qt * 128) * D + head * HD;
        #pragma unroll
        for (int i = 0; i < 8; i++) {
            int idx = tid + i * 256;
            int r = idx >> 4, c = idx & 15;
            CP16(sb + r * FA_STR + c * 16, Q + qoff + (size_t)r * D + c * 8);
        }
        CP_COMMIT();
    }

    const int kts = 2 * qt + 2;
    auto loadKV = [&](int kt) {
        const size_t koff = (size_t)(kt * 64) * KVD + kvh * HD;
        const uint32_t kb = sb + FA_KV0 + (kt & 1) * FA_KVB;
        #pragma unroll
        for (int i = 0; i < 4; i++) {
            int idx = tid + i * 256;
            int r = idx >> 4, c = idx & 15;
            size_t so = koff + (size_t)r * KVD + c * 8;
            uint32_t dst = kb + r * FA_STR + c * 16;
            CP16(dst,         K + so);
            CP16(dst + FA_KS, V + so);
        }
        CP_COMMIT();
    };
    loadKV(0);

    float m0 = -1e30f, m1 = -1e30f, l0 = 0.f, l1 = 0.f;
    float oa[16][4] = {};
    const float SC2 = 0.08838834764831845f * 1.4426950408889634f;

    for (int kt = 0; kt < kts; kt++) {
        if (kt + 1 < kts) { loadKV(kt + 1); CP_WAIT(1); }
        else              { CP_WAIT(0); }
        __syncthreads();
        const uint32_t kb = sb + FA_KV0 + (kt & 1) * FA_KVB;

        // ---- S = Q @ K^T ----
        float s[8][4];
        #pragma unroll
        for (int nf = 0; nf < 8; nf++)
            s[nf][0] = s[nf][1] = s[nf][2] = s[nf][3] = 0.f;
        #pragma unroll
        for (int ks = 0; ks < 8; ks++) {
            uint32_t af[4], bk[4][4];
            ldsm_x4(af, sb + (wid * 16 + lrow) * FA_STR + lcol + ks * 32);
            #pragma unroll
            for (int bt = 0; bt < 4; bt++)
                ldsm_x4(bk[bt], kb + (bt * 16 + lrow) * FA_STR + lcol + ks * 32);
            #pragma unroll
            for (int nf = 0; nf < 8; nf++)
                mma16816(s[nf], af, bk[nf >> 1][nf & 1], bk[nf >> 1][2 + (nf & 1)]);
        }

        // ---- causal mask (last two KV tiles overlap the diagonal) ----
        if (kt >= kts - 2) {
            int rg = qt * 128 + wid * 16 + g;
            int kbase = kt * 64;
            #pragma unroll
            for (int nf = 0; nf < 8; nf++) {
                int cg = kbase + nf * 8 + tq * 2;
                if (cg > rg)         s[nf][0] = -1e30f;
                if (cg + 1 > rg)     s[nf][1] = -1e30f;
                if (cg > rg + 8)     s[nf][2] = -1e30f;
                if (cg + 1 > rg + 8) s[nf][3] = -1e30f;
            }
        }

        float mx0 = -1e30f, mx1 = -1e30f;
        #pragma unroll
        for (int nf = 0; nf < 8; nf++) {
            mx0 = fmaxf(mx0, fmaxf(s[nf][0], s[nf][1]));
            mx1 = fmaxf(mx1, fmaxf(s[nf][2], s[nf][3]));
        }
        mx0 = fmaxf(mx0, __shfl_xor_sync(0xffffffffu, mx0, 1));
        mx0 = fmaxf(mx0, __shfl_xor_sync(0xffffffffu, mx0, 2));
        mx1 = fmaxf(mx1, __shfl_xor_sync(0xffffffffu, mx1, 1));
        mx1 = fmaxf(mx1, __shfl_xor_sync(0xffffffffu, mx1, 2));
        float mn0 = fmaxf(m0, mx0), mn1 = fmaxf(m1, mx1);
        float corr0 = ex2((m0 - mn0) * SC2);
        float corr1 = ex2((m1 - mn1) * SC2);
        m0 = mn0; m1 = mn1;
        l0 *= corr0; l1 *= corr1;
        #pragma unroll
        for (int nf = 0; nf < 8; nf++) {
            s[nf][0] = ex2((s[nf][0] - m0) * SC2);
            s[nf][1] = ex2((s[nf][1] - m0) * SC2);
            s[nf][2] = ex2((s[nf][2] - m1) * SC2);
            s[nf][3] = ex2((s[nf][3] - m1) * SC2);
            l0 += s[nf][0] + s[nf][1];
            l1 += s[nf][2] + s[nf][3];
        }
        #pragma unroll
        for (int nf = 0; nf < 16; nf++) {
            oa[nf][0] *= corr0; oa[nf][1] *= corr0;
            oa[nf][2] *= corr1; oa[nf][3] *= corr1;
        }

        // ---- O += P @ V ----
        const uint32_t vb = kb + FA_KS;
        #pragma unroll
        for (int pk = 0; pk < 4; pk++) {
            uint32_t pa[4];
            pa[0] = pk2(s[2 * pk][0],     s[2 * pk][1]);
            pa[1] = pk2(s[2 * pk][2],     s[2 * pk][3]);
            pa[2] = pk2(s[2 * pk + 1][0], s[2 * pk + 1][1]);
            pa[3] = pk2(s[2 * pk + 1][2], s[2 * pk + 1][3]);
            #pragma unroll
            for (int nbp = 0; nbp < 4; nbp++) {
                int nb0 = 2 * nbp, nb1 = 2 * nbp + 1;
                uint32_t vh0[4], vh1[4];
                ldsm_x4_t(vh0, vb + (pk * 16 + lrow) * FA_STR + nb0 * 32 + lcol);
                ldsm_x4_t(vh1, vb + (pk * 16 + lrow) * FA_STR + nb1 * 32 + lcol);
                mma16816(oa[2 * nb0],     pa, vh0[0], vh0[1]);
                mma16816(oa[2 * nb0 + 1], pa, vh0[2], vh0[3]);
                mma16816(oa[2 * nb1],     pa, vh1[0], vh1[1]);
                mma16816(oa[2 * nb1 + 1], pa, vh1[2], vh1[3]);
            }
        }
        __syncthreads();
    }

    l0 += __shfl_xor_sync(0xffffffffu, l0, 1);
    l0 += __shfl_xor_sync(0xffffffffu, l0, 2);
    l1 += __shfl_xor_sync(0xffffffffu, l1, 1);
    l1 += __shfl_xor_sync(0xffffffffu, l1, 2);
    float inv0 = 1.f / l0, inv1 = 1.f / l1;
    int row0 = qt * 128 + wid * 16 + g;
    size_t base0 = (size_t)row0 * D + head * HD + tq * 2;
    size_t base1 = base0 + 8 * D;
    #pragma unroll
    for (int nf = 0; nf < 16; nf++) {
        *(uint32_t*)(aoH + base0 + nf * 8) = pk2(oa[nf][0] * inv0, oa[nf][1] * inv0);
        *(uint32_t*)(aoH + base1 + nf * 8) = pk2(oa[nf][2] * inv1, oa[nf][3] * inv1);
    }
}

// ================= launcher =================
extern "C" void kernel_launch(void* const* d_in, const int* in_sizes, int n_in,
                              void* d_out, int out_size) {
    const float* hs  = (const float*)d_in[0];
    const float* Wq  = (const float*)d_in[1];
    const float* Wk  = (const float*)d_in[2];
    const float* Wv  = (const float*)d_in[3];
    const float* Wo  = (const float*)d_in[4];
    const float* Wr1 = (const float*)d_in[5];
    const float* br1 = (const float*)d_in[6];
    const float* Wr2 = (const float*)d_in[7];
    const float* br2 = (const float*)d_in[8];
    float* out = (float*)d_out;

    float* S;
    cudaGetSymbolAddress((void**)&S, g_scratch);
    float* q     = S;                 // fp32 q (rope input)
    float* l2    = S + 4 * MEG;
    float* h     = S + 8 * MEG;
    float* kbuf  = S + 10 * MEG;
    float* vbuf  = S + 11 * MEG;
    float* lam   = S + 12 * MEG;
    float* carry = lam + 4096;
    float* cpref = carry + 32768;
    __half* hsH   = (__half*)(S + 13 * MEG);
    __half* qH    = (__half*)(S + 15 * MEG);
    __half* fusH  = (__half*)(S + 17 * MEG);
    __half* Wt    = (__half*)(S + 19 * MEG);   // up to D*D halves
    __half* QrH   = (__half*)(S + 21 * MEG);
    __half* KrH   = (__half*)(S + 23 * MEG);
    __half* VH    = (__half*)(S + 24 * MEG);
    __half* aoH   = (__half*)(S + 25 * MEG);

    cudaFuncSetAttribute(gemm_mma<0>, cudaFuncAttributeMaxDynamicSharedMemorySize, SMEMB);
    cudaFuncSetAttribute(gemm_mma<1>, cudaFuncAttributeMaxDynamicSharedMemorySize, SMEMB);
    cudaFuncSetAttribute(fattn_kernel, cudaFuncAttributeMaxDynamicSharedMemorySize, FA_SMEM);

    // ---- q = hs @ Wq (emit fp32 q + fp16 qH) ----
    conv_a<<<(T * D / 4 + 255) / 256, 256>>>(hs, hsH, T * D / 4);
    conv_wt<<<dim3(D / 32, D / 32), 256>>>(Wq, Wt, D, D);
    gemm_mma<0><<<dim3(D / 128, T / 128, 1), 256, SMEMB>>>(
        hsH, Wt, nullptr, q, qH, T, D, D, nullptr, nullptr, nullptr);

    // ---- EMA ----
    ema1_kernel<<<dim3(16, 8), 256>>>(hs, l2, carry);
    ema2_kernel<<<8, 256>>>(carry, cpref);

    // ---- h = silu(q @ Wr1 + br1) ----
    conv_wt<<<dim3(DH / 32, D / 32), 256>>>(Wr1, Wt, D, DH);
    gemm_mma<1><<<dim3(DH / 128, T / 128, 1), 256, SMEMB>>>(
        qH, Wt, br1, h, nullptr, T, DH, D, nullptr, nullptr, nullptr);

    // ---- lam; fused -> fp16 directly ----
    router_kernel<<<T / 8, 256>>>(h, Wr2, br2, lam);
    fuse_h<<<(T * D / 2 + 255) / 256, 256>>>(hs, l2, cpref, lam, fusH);

    // ---- k = fused @ Wk (fp32), v = fused @ Wv (fp32 + fp16 VH) ----
    __half* WkT = Wt;
    __half* WvT = Wt + (size_t)KVD * D;
    conv_wt<<<dim3(KVD / 32, D / 32), 256>>>(Wk, WkT, D, KVD);
    conv_wt<<<dim3(KVD / 32, D / 32), 256>>>(Wv, WvT, D, KVD);
    gemm_mma<0><<<dim3(KVD / 128, T / 128, 2), 256, SMEMB>>>(
        fusH, WkT, nullptr, kbuf, nullptr, T, KVD, D, WvT, vbuf, VH);

    // ---- RoPE -> fp16 ----
    rope_h<<<(T * NH * 32 + 255) / 256, 256>>>(q, QrH, NH);
    rope_h<<<(T * NKVH * 32 + 255) / 256, 256>>>(kbuf, KrH, NKVH);

    // ---- flash attention -> fp16 aoH ----
    fattn_kernel<<<dim3(T / 128, NH), 256, FA_SMEM>>>(QrH, KrH, VH, aoH);

    // ---- out = ao @ Wo ----
    conv_wt<<<dim3(D / 32, D / 32), 256>>>(Wo, Wt, D, D);
    gemm_mma<0><<<dim3(D / 128, T / 128, 1), 256, SMEMB>>>(
        aoH, Wt, nullptr, out, nullptr, T, D, D, nullptr, nullptr, nullptr);
}

// round 13
// speedup vs baseline: 2.3350x; 1.0431x over previous
#include <cuda_runtime.h>
#include <cuda_fp16.h>
#include <math.h>
#include <stdint.h>

#define T 2048
#define D 2048
#define NH 16
#define NKVH 4
#define HD 128
#define DH 1024
#define KVD 512
#define MEG (1024*1024)

__device__ float g_scratch[25 * MEG];

// ================= PTX helpers =================
__device__ __forceinline__ uint32_t smem_u32(const void* p) {
    uint32_t a;
    asm("{ .reg .u64 t; cvta.to.shared.u64 t, %1; cvt.u32.u64 %0, t; }" : "=r"(a) : "l"(p));
    return a;
}
#define CP16(s, g) asm volatile("cp.async.cg.shared.global [%0], [%1], 16;" \
    :: "r"(s), "l"(__cvta_generic_to_global(g)) : "memory")
#define CP_COMMIT() asm volatile("cp.async.commit_group;" ::: "memory")
#define CP_WAIT(n)  asm volatile("cp.async.wait_group %0;" :: "n"(n) : "memory")

__device__ __forceinline__ void ldsm_x4(uint32_t* r, uint32_t addr) {
    asm volatile("ldmatrix.sync.aligned.m8n8.x4.shared.b16 {%0,%1,%2,%3}, [%4];"
        : "=r"(r[0]), "=r"(r[1]), "=r"(r[2]), "=r"(r[3]) : "r"(addr));
}
__device__ __forceinline__ void ldsm_x4_t(uint32_t* r, uint32_t addr) {
    asm volatile("ldmatrix.sync.aligned.m8n8.x4.trans.shared.b16 {%0,%1,%2,%3}, [%4];"
        : "=r"(r[0]), "=r"(r[1]), "=r"(r[2]), "=r"(r[3]) : "r"(addr));
}
__device__ __forceinline__ void mma16816(float* d, const uint32_t* a, uint32_t b0, uint32_t b1) {
    asm volatile("mma.sync.aligned.m16n8k16.row.col.f32.f16.f16.f32 "
        "{%0,%1,%2,%3}, {%4,%5,%6,%7}, {%8,%9}, {%0,%1,%2,%3};"
        : "+f"(d[0]), "+f"(d[1]), "+f"(d[2]), "+f"(d[3])
        : "r"(a[0]), "r"(a[1]), "r"(a[2]), "r"(a[3]), "r"(b0), "r"(b1));
}
__device__ __forceinline__ float ex2(float x) {
    float y; asm("ex2.approx.ftz.f32 %0, %1;" : "=f"(y) : "f"(x)); return y;
}
__device__ __forceinline__ uint32_t pk2(float a, float b) {
    __half2 h = __floats2half2_rn(a, b);
    return *(uint32_t*)&h;
}

// ================= mega-prep: ema1 + hs->fp16 + 5 weight transposes =========
// block regions: [0,128) ema1 | [128,4224) hsH | rest: conv_wt for Wq/Wr1/Wk/Wv/Wo
__global__ void prep_kernel(const float* __restrict__ hs,
                            const float* __restrict__ Wq, const float* __restrict__ Wr1,
                            const float* __restrict__ Wk, const float* __restrict__ Wv,
                            const float* __restrict__ Wo,
                            __half* __restrict__ WqT, __half* __restrict__ Wr1T,
                            __half* __restrict__ WkT, __half* __restrict__ WvT,
                            __half* __restrict__ WoT,
                            __half* __restrict__ hsH, float* __restrict__ l2,
                            float* __restrict__ carry) {
    __shared__ float tile[32][33];
    int lb = blockIdx.x;
    int tid = threadIdx.x;
    if (lb < 128) {            // ema1 (latency-bound; scheduled first)
        int c = lb >> 3;
        int d = (lb & 7) * 256 + tid;
        float m = 0.f;
        int t0 = c * 128;
        for (int t = t0; t < t0 + 128; t++) {
            m = 0.9f * m + 0.1f * hs[(size_t)t * D + d];
            l2[(size_t)t * D + d] = m;
        }
        carry[c * D + d] = m;
        return;
    }
    lb -= 128;
    if (lb < 4096) {           // hs -> fp16
        int i = lb * 256 + tid;
        float4 a = ((const float4*)hs)[i];
        ((uint32_t*)hsH)[2 * i]     = pk2(a.x, a.y);
        ((uint32_t*)hsH)[2 * i + 1] = pk2(a.z, a.w);
        return;
    }
    lb -= 4096;
    const float* W; __half* Wt; int Kd, Nd;
    if (lb < 4096)      { W = Wq;  Wt = WqT;  Kd = D; Nd = D;   }
    else if (lb < 6144) { W = Wr1; Wt = Wr1T; Kd = D; Nd = DH;  lb -= 4096; }
    else if (lb < 7168) { W = Wk;  Wt = WkT;  Kd = D; Nd = KVD; lb -= 6144; }
    else if (lb < 8192) { W = Wv;  Wt = WvT;  Kd = D; Nd = KVD; lb -= 7168; }
    else                { W = Wo;  Wt = WoT;  Kd = D; Nd = D;   lb -= 8192; }
    int ntn = Nd / 32;
    int nb = (lb % ntn) * 32, kb = (lb / ntn) * 32;
    int tx = tid & 31, ty0 = tid >> 5;
    #pragma unroll
    for (int i = 0; i < 4; i++)
        tile[ty0 + 8 * i][tx] = W[(size_t)(kb + ty0 + 8 * i) * Nd + nb + tx];
    __syncthreads();
    #pragma unroll
    for (int i = 0; i < 4; i++) {
        int r = ty0 + 8 * i;
        Wt[(size_t)(nb + r) * Kd + kb + tx] = __float2half_rn(tile[tx][r]);
    }
}

// ================= EMA pass 2 =================
__global__ void ema2_kernel(const float* __restrict__ carry, float* __restrict__ cpref) {
    int d = blockIdx.x * 256 + threadIdx.x;
    const float b128 = 1.3900845e-06f;  // 0.9^128
    float p = 0.f;
    #pragma unroll
    for (int c = 0; c < 16; c++) {
        cpref[c * D + d] = p;
        p = carry[c * D + d] + b128 * p;
    }
}

// ================= fp16 HMMA GEMM, triple-buffered =================
#define SM_STRIDE 80
#define SM_SPLIT 10240
#define SM_BUF 20480
#define SMEMB 61440

template<int ACT>
__global__ __launch_bounds__(256, 1)
void gemm_mma(const __half* __restrict__ A, const __half* __restrict__ B,
              const float* __restrict__ bias, float* __restrict__ C,
              __half* __restrict__ Chi,
              int M, int N, int K,
              const __half* B2, float* C2, __half* C2hi) {
    extern __shared__ char smem[];
    if (blockIdx.z) { B = B2; C = C2; Chi = C2hi; }
    const int tid = threadIdx.x, wid = tid >> 5, lane = tid & 31;
    const int m0 = blockIdx.y * 128, n0 = blockIdx.x * 128;
    const int wm = wid >> 2, wn = wid & 3;
    const uint32_t sb = smem_u32(smem);

    const int r0c = tid >> 2, c0c = (tid & 3);
    const int r1c = (tid + 256) >> 2, c1c = (tid & 3);

    auto fill = [&](int buf, int kc) {
        const int k0 = kc << 5;
        const uint32_t s0 = sb + buf * SM_BUF;
        uint32_t so0 = r0c * SM_STRIDE + c0c * 16;
        uint32_t so1 = r1c * SM_STRIDE + c1c * 16;
        CP16(s0 + so0, A + (size_t)(m0 + r0c) * K + k0 + c0c * 8);
        CP16(s0 + so1, A + (size_t)(m0 + r1c) * K + k0 + c1c * 8);
        CP16(s0 + SM_SPLIT + so0, B + (size_t)(n0 + r0c) * K + k0 + c0c * 8);
        CP16(s0 + SM_SPLIT + so1, B + (size_t)(n0 + r1c) * K + k0 + c1c * 8);
        CP_COMMIT();
    };

    float acc[4][4][4] = {};
    const int KC = K >> 5;
    fill(0, 0);
    if (KC > 1) fill(1, 1);
    for (int kc = 0; kc < KC; kc++) {
        if (kc + 2 < KC) { fill((kc + 2) % 3, kc + 2); CP_WAIT(2); }
        else if (kc + 1 < KC) { CP_WAIT(1); }
        else { CP_WAIT(0); }
        __syncthreads();
        const uint32_t base = sb + (kc % 3) * SM_BUF;
        const uint32_t lrow = (lane & 15), lcol = (lane >> 4) * 16;
        #pragma unroll
        for (int kh = 0; kh < 2; kh++) {
            uint32_t af[4][4], bf[2][4];
            #pragma unroll
            for (int mt = 0; mt < 4; mt++)
                ldsm_x4(af[mt], base + (wm * 64 + mt * 16 + lrow) * SM_STRIDE + kh * 32 + lcol);
            #pragma unroll
            for (int nt = 0; nt < 2; nt++)
                ldsm_x4(bf[nt], base + SM_SPLIT + (wn * 32 + nt * 16 + lrow) * SM_STRIDE + kh * 32 + lcol);
            #pragma unroll
            for (int mt = 0; mt < 4; mt++)
                #pragma unroll
                for (int j = 0; j < 4; j++)
                    mma16816(acc[mt][j], af[mt], bf[j >> 1][j & 1], bf[j >> 1][2 + (j & 1)]);
        }
        __syncthreads();
    }

    const int erow = m0 + wm * 64 + (lane >> 2);
    const int ecol = n0 + wn * 32 + (lane & 3) * 2;
    #pragma unroll
    for (int mt = 0; mt < 4; mt++)
        #pragma unroll
        for (int j = 0; j < 4; j++) {
            int r = erow + mt * 16, c = ecol + j * 8;
            float v0 = acc[mt][j][0], v1 = acc[mt][j][1];
            float v2 = acc[mt][j][2], v3 = acc[mt][j][3];
            if (ACT) {
                float b0 = bias[c], b1 = bias[c + 1];
                v0 += b0; v1 += b1; v2 += b0; v3 += b1;
                v0 = v0 / (1.f + expf(-v0)); v1 = v1 / (1.f + expf(-v1));
                v2 = v2 / (1.f + expf(-v2)); v3 = v3 / (1.f + expf(-v3));
            }
            if (C) {
                *(float2*)(C + (size_t)r * N + c)       = make_float2(v0, v1);
                *(float2*)(C + (size_t)(r + 8) * N + c) = make_float2(v2, v3);
            }
            if (Chi) {
                *(uint32_t*)(Chi + (size_t)r * N + c)       = pk2(v0, v1);
                *(uint32_t*)(Chi + (size_t)(r + 8) * N + c) = pk2(v2, v3);
            }
        }
}

// ================= router + fuse (one block per token) =================
__global__ void router_fuse(const float* __restrict__ h, const float* __restrict__ Wr2,
                            const float* __restrict__ br2, const float* __restrict__ x,
                            const float* __restrict__ l2, const float* __restrict__ cpref,
                            __half* __restrict__ fh) {
    __shared__ float red[16];
    __shared__ float lamS[2];
    int t = blockIdx.x, tid = threadIdx.x, wid = tid >> 5, lane = tid & 31;
    const float* hp = h + (size_t)t * DH;
    float4 hv  = *(const float4*)(hp + tid * 4);
    float4 w01 = *(const float4*)(Wr2 + tid * 8);
    float4 w23 = *(const float4*)(Wr2 + tid * 8 + 4);
    float z0 = hv.x * w01.x + hv.y * w01.z + hv.z * w23.x + hv.w * w23.z;
    float z1 = hv.x * w01.y + hv.y * w01.w + hv.z * w23.y + hv.w * w23.w;
    #pragma unroll
    for (int off = 16; off; off >>= 1) {
        z0 += __shfl_xor_sync(0xffffffffu, z0, off);
        z1 += __shfl_xor_sync(0xffffffffu, z1, off);
    }
    if (lane == 0) { red[wid] = z0; red[8 + wid] = z1; }
    __syncthreads();
    if (tid == 0) {
        float a = 0.f, b = 0.f;
        #pragma unroll
        for (int i = 0; i < 8; i++) { a += red[i]; b += red[8 + i]; }
        a += br2[0]; b += br2[1];
        float mx = fmaxf(a, b);
        float e0 = expf(a - mx), e1 = expf(b - mx);
        float inv = 1.f / (e0 + e1);
        lamS[0] = e0 * inv; lamS[1] = e1 * inv;
    }
    __syncthreads();
    float la = lamS[0], lb = lamS[1];
    int c = t >> 7, tl = t & 127;
    float w = __expf((float)(tl + 1) * -0.10536051565f);
    size_t rowo = (size_t)t * D;
    #pragma unroll
    for (int i = 0; i < 2; i++) {
        int e = tid * 8 + i * 4;
        float4 xv = *(const float4*)(x + rowo + e);
        float4 lv = *(const float4*)(l2 + rowo + e);
        float4 cp = *(const float4*)(cpref + c * D + e);
        float f0 = la * xv.x + lb * (lv.x + w * cp.x);
        float f1 = la * xv.y + lb * (lv.y + w * cp.y);
        float f2 = la * xv.z + lb * (lv.z + w * cp.z);
        float f3 = la * xv.w + lb * (lv.w + w * cp.w);
        ((uint32_t*)fh)[(rowo + e) / 2]     = pk2(f0, f1);
        ((uint32_t*)fh)[(rowo + e) / 2 + 1] = pk2(f2, f3);
    }
}

// ================= RoPE (fp16 in, fp16 out) =================
__global__ void rope_h(const __half* __restrict__ x, __half* __restrict__ o, int heads) {
    int idx = blockIdx.x * blockDim.x + threadIdx.x;
    int total = T * heads * 32;
    if (idx >= total) return;
    int jp = idx & 31;
    int hh = (idx >> 5) % heads;
    int t = idx / (heads * 32);
    int j = jp * 2;
    const float LN = 0.1439115683121279f;  // ln(10000)/64
    float inv0 = expf(-LN * j), inv1 = expf(-LN * (j + 1));
    float c0, s0, c1, s1;
    sincosf((float)t * inv0, &s0, &c0);
    sincosf((float)t * inv1, &s1, &c1);
    size_t base = (size_t)t * heads * HD + hh * HD;
    __half2 plo = *(const __half2*)(x + base + j);
    __half2 phi = *(const __half2*)(x + base + j + 64);
    float a0 = __low2float(plo), a1 = __high2float(plo);
    float b0 = __low2float(phi), b1 = __high2float(phi);
    *(uint32_t*)(o + base + j)      = pk2(a0 * c0 - b0 * s0, a1 * c1 - b1 * s1);
    *(uint32_t*)(o + base + j + 64) = pk2(b0 * c0 + a0 * s0, b1 * c1 + a1 * s1);
}

// ===== tensor-core flash attention (256 thr, 128-row Q tile, pure fp16) =====
#define FA_STR 272
#define FA_QS 34816
#define FA_KS 17408
#define FA_KVB 34816
#define FA_KV0 34816
#define FA_SMEM 104448

__global__ __launch_bounds__(256, 1)
void fattn_kernel(const __half* __restrict__ Q, const __half* __restrict__ K,
                  const __half* __restrict__ V, __half* __restrict__ aoH) {
    extern __shared__ char smem[];
    const int tid = threadIdx.x, wid = tid >> 5, lane = tid & 31;
    const int qt = (int)(gridDim.x - 1 - blockIdx.x);   // long CTAs first
    const int head = blockIdx.y;
    const int kvh = head >> 2;
    const uint32_t sb = smem_u32(smem);
    const int g = lane >> 2, tq = lane & 3;
    const uint32_t lrow = lane & 15, lcol = (lane >> 4) * 16;

    {
        const size_t qoff = (size_t)(qt * 128) * D + head * HD;
        #pragma unroll
        for (int i = 0; i < 8; i++) {
            int idx = tid + i * 256;
            int r = idx >> 4, c = idx & 15;
            CP16(sb + r * FA_STR + c * 16, Q + qoff + (size_t)r * D + c * 8);
        }
        CP_COMMIT();
    }

    const int kts = 2 * qt + 2;
    auto loadKV = [&](int kt) {
        const size_t koff = (size_t)(kt * 64) * KVD + kvh * HD;
        const uint32_t kb = sb + FA_KV0 + (kt & 1) * FA_KVB;
        #pragma unroll
        for (int i = 0; i < 4; i++) {
            int idx = tid + i * 256;
            int r = idx >> 4, c = idx & 15;
            size_t so = koff + (size_t)r * KVD + c * 8;
            uint32_t dst = kb + r * FA_STR + c * 16;
            CP16(dst,         K + so);
            CP16(dst + FA_KS, V + so);
        }
        CP_COMMIT();
    };
    loadKV(0);

    float m0 = -1e30f, m1 = -1e30f, l0 = 0.f, l1 = 0.f;
    float oa[16][4] = {};
    const float SC2 = 0.08838834764831845f * 1.4426950408889634f;

    for (int kt = 0; kt < kts; kt++) {
        if (kt + 1 < kts) { loadKV(kt + 1); CP_WAIT(1); }
        else              { CP_WAIT(0); }
        __syncthreads();
        const uint32_t kb = sb + FA_KV0 + (kt & 1) * FA_KVB;

        float s[8][4];
        #pragma unroll
        for (int nf = 0; nf < 8; nf++)
            s[nf][0] = s[nf][1] = s[nf][2] = s[nf][3] = 0.f;
        #pragma unroll
        for (int ks = 0; ks < 8; ks++) {
            uint32_t af[4], bk[4][4];
            ldsm_x4(af, sb + (wid * 16 + lrow) * FA_STR + lcol + ks * 32);
            #pragma unroll
            for (int bt = 0; bt < 4; bt++)
                ldsm_x4(bk[bt], kb + (bt * 16 + lrow) * FA_STR + lcol + ks * 32);
            #pragma unroll
            for (int nf = 0; nf < 8; nf++)
                mma16816(s[nf], af, bk[nf >> 1][nf & 1], bk[nf >> 1][2 + (nf & 1)]);
        }

        if (kt >= kts - 2) {
            int rg = qt * 128 + wid * 16 + g;
            int kbase = kt * 64;
            #pragma unroll
            for (int nf = 0; nf < 8; nf++) {
                int cg = kbase + nf * 8 + tq * 2;
                if (cg > rg)         s[nf][0] = -1e30f;
                if (cg + 1 > rg)     s[nf][1] = -1e30f;
                if (cg > rg + 8)     s[nf][2] = -1e30f;
                if (cg + 1 > rg + 8) s[nf][3] = -1e30f;
            }
        }

        float mx0 = -1e30f, mx1 = -1e30f;
        #pragma unroll
        for (int nf = 0; nf < 8; nf++) {
            mx0 = fmaxf(mx0, fmaxf(s[nf][0], s[nf][1]));
            mx1 = fmaxf(mx1, fmaxf(s[nf][2], s[nf][3]));
        }
        mx0 = fmaxf(mx0, __shfl_xor_sync(0xffffffffu, mx0, 1));
        mx0 = fmaxf(mx0, __shfl_xor_sync(0xffffffffu, mx0, 2));
        mx1 = fmaxf(mx1, __shfl_xor_sync(0xffffffffu, mx1, 1));
        mx1 = fmaxf(mx1, __shfl_xor_sync(0xffffffffu, mx1, 2));
        float mn0 = fmaxf(m0, mx0), mn1 = fmaxf(m1, mx1);
        float corr0 = ex2((m0 - mn0) * SC2);
        float corr1 = ex2((m1 - mn1) * SC2);
        m0 = mn0; m1 = mn1;
        l0 *= corr0; l1 *= corr1;
        #pragma unroll
        for (int nf = 0; nf < 8; nf++) {
            s[nf][0] = ex2((s[nf][0] - m0) * SC2);
            s[nf][1] = ex2((s[nf][1] - m0) * SC2);
            s[nf][2] = ex2((s[nf][2] - m1) * SC2);
            s[nf][3] = ex2((s[nf][3] - m1) * SC2);
            l0 += s[nf][0] + s[nf][1];
            l1 += s[nf][2] + s[nf][3];
        }
        #pragma unroll
        for (int nf = 0; nf < 16; nf++) {
            oa[nf][0] *= corr0; oa[nf][1] *= corr0;
            oa[nf][2] *= corr1; oa[nf][3] *= corr1;
        }

        const uint32_t vb = kb + FA_KS;
        #pragma unroll
        for (int pk = 0; pk < 4; pk++) {
            uint32_t pa[4];
            pa[0] = pk2(s[2 * pk][0],     s[2 * pk][1]);
            pa[1] = pk2(s[2 * pk][2],     s[2 * pk][3]);
            pa[2] = pk2(s[2 * pk + 1][0], s[2 * pk + 1][1]);
            pa[3] = pk2(s[2 * pk + 1][2], s[2 * pk + 1][3]);
            #pragma unroll
            for (int nbp = 0; nbp < 4; nbp++) {
                int nb0 = 2 * nbp, nb1 = 2 * nbp + 1;
                uint32_t vh0[4], vh1[4];
                ldsm_x4_t(vh0, vb + (pk * 16 + lrow) * FA_STR + nb0 * 32 + lcol);
                ldsm_x4_t(vh1, vb + (pk * 16 + lrow) * FA_STR + nb1 * 32 + lcol);
                mma16816(oa[2 * nb0],     pa, vh0[0], vh0[1]);
                mma16816(oa[2 * nb0 + 1], pa, vh0[2], vh0[3]);
                mma16816(oa[2 * nb1],     pa, vh1[0], vh1[1]);
                mma16816(oa[2 * nb1 + 1], pa, vh1[2], vh1[3]);
            }
        }
        __syncthreads();
    }

    l0 += __shfl_xor_sync(0xffffffffu, l0, 1);
    l0 += __shfl_xor_sync(0xffffffffu, l0, 2);
    l1 += __shfl_xor_sync(0xffffffffu, l1, 1);
    l1 += __shfl_xor_sync(0xffffffffu, l1, 2);
    float inv0 = 1.f / l0, inv1 = 1.f / l1;
    int row0 = qt * 128 + wid * 16 + g;
    size_t base0 = (size_t)row0 * D + head * HD + tq * 2;
    size_t base1 = base0 + 8 * D;
    #pragma unroll
    for (int nf = 0; nf < 16; nf++) {
        *(uint32_t*)(aoH + base0 + nf * 8) = pk2(oa[nf][0] * inv0, oa[nf][1] * inv0);
        *(uint32_t*)(aoH + base1 + nf * 8) = pk2(oa[nf][2] * inv1, oa[nf][3] * inv1);
    }
}

// ================= launcher =================
extern "C" void kernel_launch(void* const* d_in, const int* in_sizes, int n_in,
                              void* d_out, int out_size) {
    const float* hs  = (const float*)d_in[0];
    const float* Wq  = (const float*)d_in[1];
    const float* Wk  = (const float*)d_in[2];
    const float* Wv  = (const float*)d_in[3];
    const float* Wo  = (const float*)d_in[4];
    const float* Wr1 = (const float*)d_in[5];
    const float* br1 = (const float*)d_in[6];
    const float* Wr2 = (const float*)d_in[7];
    const float* br2 = (const float*)d_in[8];
    float* out = (float*)d_out;

    float* S;
    cudaGetSymbolAddress((void**)&S, g_scratch);
    float* l2    = S;                        // [0,4M)
    float* h     = S + 4 * MEG;              // [4M,6M)
    float* lam   = S + 6 * MEG;
    float* carry = lam + 4096;
    float* cpref = carry + 32768;
    __half* hsH  = (__half*)(S + 7 * MEG);   // 2M floats
    __half* qH   = (__half*)(S + 9 * MEG);
    __half* fusH = (__half*)(S + 11 * MEG);
    __half* WqT  = (__half*)(S + 13 * MEG);
    __half* Wr1T = (__half*)(S + 15 * MEG);
    __half* WkT  = (__half*)(S + 16 * MEG);
    __half* WvT  = (__half*)(S + 16 * MEG + 512 * 1024);
    __half* WoT  = (__half*)(S + 17 * MEG);
    __half* kH   = (__half*)(S + 19 * MEG);
    __half* VH   = (__half*)(S + 19 * MEG + 512 * 1024);
    __half* QrH  = (__half*)(S + 20 * MEG);
    __half* KrH  = (__half*)(S + 22 * MEG);
    __half* aoH  = (__half*)(S + 23 * MEG);

    cudaFuncSetAttribute(gemm_mma<0>, cudaFuncAttributeMaxDynamicSharedMemorySize, SMEMB);
    cudaFuncSetAttribute(gemm_mma<1>, cudaFuncAttributeMaxDynamicSharedMemorySize, SMEMB);
    cudaFuncSetAttribute(fattn_kernel, cudaFuncAttributeMaxDynamicSharedMemorySize, FA_SMEM);

    // ---- prep: ema1 + hs fp16 + all weight transposes (one launch) ----
    prep_kernel<<<16512, 256>>>(hs, Wq, Wr1, Wk, Wv, Wo,
                                WqT, Wr1T, WkT, WvT, WoT, hsH, l2, carry);
    ema2_kernel<<<8, 256>>>(carry, cpref);

    // ---- q = hs @ Wq (fp16 out only) ----
    gemm_mma<0><<<dim3(D / 128, T / 128, 1), 256, SMEMB>>>(
        hsH, WqT, nullptr, nullptr, qH, T, D, D, nullptr, nullptr, nullptr);

    // ---- h = silu(q @ Wr1 + br1) (fp32 out) ----
    gemm_mma<1><<<dim3(DH / 128, T / 128, 1), 256, SMEMB>>>(
        qH, Wr1T, br1, h, nullptr, T, DH, D, nullptr, nullptr, nullptr);

    // ---- router + fuse -> fp16 fused ----
    router_fuse<<<T, 256>>>(h, Wr2, br2, hs, l2, cpref, fusH);

    // ---- k/v = fused @ Wk/Wv (fp16 out only) ----
    gemm_mma<0><<<dim3(KVD / 128, T / 128, 2), 256, SMEMB>>>(
        fusH, WkT, nullptr, nullptr, kH, T, KVD, D, WvT, nullptr, VH);

    // ---- RoPE (fp16 in/out) ----
    rope_h<<<(T * NH * 32 + 255) / 256, 256>>>(qH, QrH, NH);
    rope_h<<<(T * NKVH * 32 + 255) / 256, 256>>>(kH, KrH, NKVH);

    // ---- flash attention -> fp16 aoH ----
    fattn_kernel<<<dim3(T / 128, NH), 256, FA_SMEM>>>(QrH, KrH, VH, aoH);

    // ---- out = ao @ Wo (fp32 out) ----
    gemm_mma<0><<<dim3(D / 128, T / 128, 1), 256, SMEMB>>>(
        aoH, WoT, nullptr, out, nullptr, T, D, D, nullptr, nullptr, nullptr);
}